// round 2
// baseline (speedup 1.0000x reference)
#include <cuda_runtime.h>
#include <cuda_bf16.h>
#include <math.h>

#define NN 50000
#define EE 800000
#define EP 850000      // edges + self loops
#define IN_F 64
#define HID 64
#define HEADS 4
#define C1 16
#define OUT_F 32
#define NEG_SLOPE 0.2f

// ---------------- scratch (static device memory, no allocs) ----------------
__device__ float g_h1[NN * HID];        // layer-1 transformed features
__device__ float g_as1[NN * HEADS];     // alpha_src per node/head
__device__ float g_ad1[NN * HEADS];     // alpha_dst per node/head
__device__ float g_m1[NN * HEADS];      // segment max
__device__ float g_den1[NN * HEADS];    // segment sum of exp
__device__ float g_ee1[EP * HEADS];     // per-edge exp values
__device__ float g_agg1[NN * HID];      // layer-1 aggregate (pre relu+bias)
__device__ float g_h2[NN * OUT_F];      // layer-2 transformed features
__device__ float g_as2[NN];
__device__ float g_ad2[NN];
__device__ float g_m2[NN];
__device__ float g_den2[NN];
__device__ float g_ee2[EP];

// ---------------- helpers ----------------
__device__ __forceinline__ float leaky(float v) {
    return v > 0.f ? v : NEG_SLOPE * v;
}

__device__ __forceinline__ void atomicMaxFloat(float* addr, float value) {
    if (value >= 0.f)
        atomicMax((int*)addr, __float_as_int(value));
    else
        atomicMin((unsigned int*)addr, __float_as_uint(value));
}

// edge_index is int32 (JAX x64 disabled: jnp.int64 request silently yields int32)
__device__ __forceinline__ void edge_endpoints(const int* __restrict__ ei,
                                               int e, int& src, int& dst) {
    if (e < EE) {
        src = ei[e];
        dst = ei[EE + e];
    } else {
        src = dst = e - EE;   // self loop
    }
}

// ---------------- kernels ----------------

// init scratch + output (out pre-filled with bias b2)
__global__ void init_kernel(float* __restrict__ out, const float* __restrict__ b2) {
    int i = blockIdx.x * 256 + threadIdx.x;
    if (i < NN * HID)   g_agg1[i] = 0.f;
    if (i < NN * HEADS) { g_m1[i] = -INFINITY; g_den1[i] = 0.f; }
    if (i < NN)         { g_m2[i] = -INFINITY; g_den2[i] = 0.f; }
    if (i < NN * OUT_F) out[i] = b2[i & (OUT_F - 1)];
}

// h1 = x @ W1^T ; alpha_src/dst per node/head. 4 nodes x 64 outputs per block.
__global__ void gemm1_kernel(const float* __restrict__ x,
                             const float* __restrict__ W1,
                             const float* __restrict__ a_src,
                             const float* __restrict__ a_dst) {
    __shared__ float Wt[IN_F * HID];   // transposed: Wt[k*64+o] = W1[o][k]
    __shared__ float xs[4 * IN_F];
    __shared__ float av[HID], bv[HID];
    int tid = threadIdx.x;

    for (int i = tid; i < IN_F * HID; i += 256) {
        int o = i >> 6, k = i & 63;
        Wt[k * HID + o] = W1[o * IN_F + k];
    }
    if (tid < HID) { av[tid] = a_src[tid]; bv[tid] = a_dst[tid]; }
    xs[tid] = x[(long long)blockIdx.x * 4 * IN_F + tid];
    __syncthreads();

    int nl = tid >> 6;       // node-in-block 0..3
    int o  = tid & 63;       // output feature
    int node = blockIdx.x * 4 + nl;

    float acc = 0.f;
#pragma unroll
    for (int k = 0; k < IN_F; k++)
        acc = fmaf(xs[nl * IN_F + k], Wt[k * HID + o], acc);

    g_h1[(long long)node * HID + o] = acc;

    float ps = acc * av[o];
    float pd = acc * bv[o];
#pragma unroll
    for (int off = 8; off; off >>= 1) {
        ps += __shfl_xor_sync(0xffffffffu, ps, off);
        pd += __shfl_xor_sync(0xffffffffu, pd, off);
    }
    if ((o & 15) == 0) {
        int head = o >> 4;
        g_as1[node * HEADS + head] = ps;
        g_ad1[node * HEADS + head] = pd;
    }
}

// per-edge segment max (layer 1, 4 heads)
__global__ void edge_max1(const int* __restrict__ ei) {
    int e = blockIdx.x * 256 + threadIdx.x;
    if (e >= EP) return;
    int src, dst;
    edge_endpoints(ei, e, src, dst);
    float4 as = *(const float4*)(g_as1 + src * HEADS);
    float4 ad = *(const float4*)(g_ad1 + dst * HEADS);
    atomicMaxFloat(&g_m1[dst * HEADS + 0], leaky(as.x + ad.x));
    atomicMaxFloat(&g_m1[dst * HEADS + 1], leaky(as.y + ad.y));
    atomicMaxFloat(&g_m1[dst * HEADS + 2], leaky(as.z + ad.z));
    atomicMaxFloat(&g_m1[dst * HEADS + 3], leaky(as.w + ad.w));
}

// per-edge exp + segment sum (layer 1)
__global__ void edge_exp1(const int* __restrict__ ei) {
    int e = blockIdx.x * 256 + threadIdx.x;
    if (e >= EP) return;
    int src, dst;
    edge_endpoints(ei, e, src, dst);
    float4 as = *(const float4*)(g_as1 + src * HEADS);
    float4 ad = *(const float4*)(g_ad1 + dst * HEADS);
    float4 m  = *(const float4*)(g_m1  + dst * HEADS);
    float4 ee;
    ee.x = __expf(leaky(as.x + ad.x) - m.x);
    ee.y = __expf(leaky(as.y + ad.y) - m.y);
    ee.z = __expf(leaky(as.z + ad.z) - m.z);
    ee.w = __expf(leaky(as.w + ad.w) - m.w);
    *(float4*)(g_ee1 + e * HEADS) = ee;
    atomicAdd(&g_den1[dst * HEADS + 0], ee.x);
    atomicAdd(&g_den1[dst * HEADS + 1], ee.y);
    atomicAdd(&g_den1[dst * HEADS + 2], ee.z);
    atomicAdd(&g_den1[dst * HEADS + 3], ee.w);
}

// weighted aggregation (layer 1): one warp per edge, 2 features per lane
__global__ void agg1_kernel(const int* __restrict__ ei) {
    int lane = threadIdx.x & 31;
    int e = (blockIdx.x * 256 + threadIdx.x) >> 5;
    if (e >= EP) return;
    int src, dst;
    edge_endpoints(ei, e, src, dst);
    int h0 = lane >> 4;                  // head for feature `lane`
    float a0 = g_ee1[e * HEADS + h0]     / g_den1[dst * HEADS + h0];
    float a1 = g_ee1[e * HEADS + h0 + 2] / g_den1[dst * HEADS + h0 + 2];
    float v0 = g_h1[(long long)src * HID + lane]      * a0;
    float v1 = g_h1[(long long)src * HID + lane + 32] * a1;
    atomicAdd(&g_agg1[(long long)dst * HID + lane],      v0);
    atomicAdd(&g_agg1[(long long)dst * HID + lane + 32], v1);
}

// h2 = relu(agg1 + b1) @ W2^T ; alpha2. 8 nodes x 32 outputs per block.
__global__ void gemm2_kernel(const float* __restrict__ W2,
                             const float* __restrict__ b1,
                             const float* __restrict__ a_src,
                             const float* __restrict__ a_dst) {
    __shared__ float Wt[HID * OUT_F];   // Wt[k*32+j] = W2[j][k]
    __shared__ float xs[8 * HID];
    __shared__ float av[OUT_F], bv[OUT_F], b1s[HID];
    int tid = threadIdx.x;

    for (int i = tid; i < HID * OUT_F; i += 256) {
        int j = i >> 6, k = i & 63;
        Wt[k * OUT_F + j] = W2[j * HID + k];
    }
    if (tid < OUT_F) { av[tid] = a_src[tid]; bv[tid] = a_dst[tid]; }
    if (tid < HID)   b1s[tid] = b1[tid];
    __syncthreads();

    long long base = (long long)blockIdx.x * 8 * HID;
#pragma unroll
    for (int i = tid; i < 8 * HID; i += 256)
        xs[i] = fmaxf(g_agg1[base + i] + b1s[i & 63], 0.f);
    __syncthreads();

    int nl = tid >> 5;
    int j  = tid & 31;
    int node = blockIdx.x * 8 + nl;

    float acc = 0.f;
#pragma unroll
    for (int k = 0; k < HID; k++)
        acc = fmaf(xs[nl * HID + k], Wt[k * OUT_F + j], acc);

    g_h2[(long long)node * OUT_F + j] = acc;

    float ps = acc * av[j];
    float pd = acc * bv[j];
#pragma unroll
    for (int off = 16; off; off >>= 1) {
        ps += __shfl_xor_sync(0xffffffffu, ps, off);
        pd += __shfl_xor_sync(0xffffffffu, pd, off);
    }
    if (j == 0) { g_as2[node] = ps; g_ad2[node] = pd; }
}

__global__ void edge_max2(const int* __restrict__ ei) {
    int e = blockIdx.x * 256 + threadIdx.x;
    if (e >= EP) return;
    int src, dst;
    edge_endpoints(ei, e, src, dst);
    atomicMaxFloat(&g_m2[dst], leaky(g_as2[src] + g_ad2[dst]));
}

__global__ void edge_exp2(const int* __restrict__ ei) {
    int e = blockIdx.x * 256 + threadIdx.x;
    if (e >= EP) return;
    int src, dst;
    edge_endpoints(ei, e, src, dst);
    float ee = __expf(leaky(g_as2[src] + g_ad2[dst]) - g_m2[dst]);
    g_ee2[e] = ee;
    atomicAdd(&g_den2[dst], ee);
}

// layer-2 aggregation: one warp per edge, 1 feature per lane -> output
__global__ void agg2_kernel(const int* __restrict__ ei, float* __restrict__ out) {
    int lane = threadIdx.x & 31;
    int e = (blockIdx.x * 256 + threadIdx.x) >> 5;
    if (e >= EP) return;
    int src, dst;
    edge_endpoints(ei, e, src, dst);
    float alpha = g_ee2[e] / g_den2[dst];
    float v = g_h2[(long long)src * OUT_F + lane] * alpha;
    atomicAdd(&out[(long long)dst * OUT_F + lane], v);
}

// ---------------- launch ----------------
extern "C" void kernel_launch(void* const* d_in, const int* in_sizes, int n_in,
                              void* d_out, int out_size) {
    const float* x      = (const float*)d_in[0];
    const int*   ei     = (const int*)d_in[1];
    const float* W1     = (const float*)d_in[2];
    const float* a_src1 = (const float*)d_in[3];
    const float* a_dst1 = (const float*)d_in[4];
    const float* b1     = (const float*)d_in[5];
    const float* W2     = (const float*)d_in[6];
    const float* a_src2 = (const float*)d_in[7];
    const float* a_dst2 = (const float*)d_in[8];
    const float* b2     = (const float*)d_in[9];
    float* out = (float*)d_out;

    const int edge_blocks = (EP + 255) / 256;       // thread-per-edge kernels
    const int warp_edge_blocks = (EP + 7) / 8;      // warp-per-edge kernels

    init_kernel<<<(NN * HID + 255) / 256, 256>>>(out, b2);
    gemm1_kernel<<<NN / 4, 256>>>(x, W1, a_src1, a_dst1);
    edge_max1<<<edge_blocks, 256>>>(ei);
    edge_exp1<<<edge_blocks, 256>>>(ei);
    agg1_kernel<<<warp_edge_blocks, 256>>>(ei);
    gemm2_kernel<<<NN / 8, 256>>>(W2, b1, a_src2, a_dst2);
    edge_max2<<<edge_blocks, 256>>>(ei);
    edge_exp2<<<edge_blocks, 256>>>(ei);
    agg2_kernel<<<warp_edge_blocks, 256>>>(ei, out);
}

// round 3
// speedup vs baseline: 1.2288x; 1.2288x over previous
#include <cuda_runtime.h>
#include <cuda_bf16.h>
#include <math.h>

#define NN 50000
#define EE 800000
#define EP 850000      // edges + self loops
#define IN_F 64
#define HID 64
#define HEADS 4
#define OUT_F 32
#define NEG_SLOPE 0.2f

// ---------------- scratch (static device memory, no allocs) ----------------
__device__ float g_h1[NN * HID];        // layer-1 transformed features
__device__ float g_as1[NN * HEADS];
__device__ float g_ad1[NN * HEADS];
__device__ float g_agg1[NN * HID];      // layer-1 aggregate (pre relu+bias)
__device__ float g_h2[NN * OUT_F];
__device__ float g_as2[NN];
__device__ float g_ad2[NN];
__device__ int   g_deg[NN];             // in-degree (incl self loop)
__device__ int   g_rowstart[NN + 1];    // CSR row offsets (by dst)
__device__ int   g_cur[NN];             // scatter cursors
__device__ int   g_col[EP];             // CSR column (src) indices

__device__ __forceinline__ float leaky(float v) {
    return v > 0.f ? v : NEG_SLOPE * v;
}

// ---------------- kernels ----------------

// init: deg=1 (self loop pre-counted)
__global__ void init_kernel() {
    int i = blockIdx.x * 256 + threadIdx.x;
    if (i < NN) g_deg[i] = 1;
}

// histogram of dst (real edges only)
__global__ void hist_kernel(const int* __restrict__ ei) {
    int e = blockIdx.x * 256 + threadIdx.x;
    if (e < EE) atomicAdd(&g_deg[ei[EE + e]], 1);
}

// single-block chunked Hillis-Steele scan: g_rowstart = exclusive prefix of g_deg
__global__ void scan_kernel() {
    __shared__ int s[1024];
    __shared__ int carry_s;
    int tid = threadIdx.x;
    if (tid == 0) { carry_s = 0; g_rowstart[0] = 0; }
    __syncthreads();
    for (int base = 0; base < NN; base += 1024) {
        int i = base + tid;
        int v = (i < NN) ? g_deg[i] : 0;
        s[tid] = v;
        __syncthreads();
        for (int off = 1; off < 1024; off <<= 1) {
            int t = (tid >= off) ? s[tid - off] : 0;
            __syncthreads();
            s[tid] += t;
            __syncthreads();
        }
        int c = carry_s;
        int incl = s[tid];
        if (i < NN) g_rowstart[i + 1] = c + incl;
        __syncthreads();
        if (tid == 1023) carry_s = c + s[1023];
        __syncthreads();
    }
}

__global__ void cursor_kernel() {
    int i = blockIdx.x * 256 + threadIdx.x;
    if (i < NN) g_cur[i] = g_rowstart[i];
}

// scatter edges (incl self loops) into CSR buckets by dst
__global__ void scatter_kernel(const int* __restrict__ ei) {
    int e = blockIdx.x * 256 + threadIdx.x;
    if (e >= EP) return;
    int src, dst;
    if (e < EE) { src = ei[e]; dst = ei[EE + e]; }
    else        { src = dst = e - EE; }
    int pos = atomicAdd(&g_cur[dst], 1);
    g_col[pos] = src;
}

// h1 = x @ W1^T ; alpha_src/dst per node/head. 4 nodes x 64 outputs per block.
__global__ void gemm1_kernel(const float* __restrict__ x,
                             const float* __restrict__ W1,
                             const float* __restrict__ a_src,
                             const float* __restrict__ a_dst) {
    __shared__ float Wt[IN_F * HID];
    __shared__ float xs[4 * IN_F];
    __shared__ float av[HID], bv[HID];
    int tid = threadIdx.x;

    for (int i = tid; i < IN_F * HID; i += 256) {
        int o = i >> 6, k = i & 63;
        Wt[k * HID + o] = W1[o * IN_F + k];
    }
    if (tid < HID) { av[tid] = a_src[tid]; bv[tid] = a_dst[tid]; }
    xs[tid] = x[(long long)blockIdx.x * 4 * IN_F + tid];
    __syncthreads();

    int nl = tid >> 6;
    int o  = tid & 63;
    int node = blockIdx.x * 4 + nl;

    float acc = 0.f;
#pragma unroll
    for (int k = 0; k < IN_F; k++)
        acc = fmaf(xs[nl * IN_F + k], Wt[k * HID + o], acc);

    g_h1[node * HID + o] = acc;

    float ps = acc * av[o];
    float pd = acc * bv[o];
#pragma unroll
    for (int off = 8; off; off >>= 1) {
        ps += __shfl_xor_sync(0xffffffffu, ps, off);
        pd += __shfl_xor_sync(0xffffffffu, pd, off);
    }
    if ((o & 15) == 0) {
        int head = o >> 4;
        g_as1[node * HEADS + head] = ps;
        g_ad1[node * HEADS + head] = pd;
    }
}

// fused layer-1 edge softmax + aggregation: one warp per dst node, no atomics.
// out[dst] = (sum_e ee_e * h1[src_e]) / denom   (per head)
__global__ void fused_agg1(const int* __restrict__ col) {
    int warp = (blockIdx.x * blockDim.x + threadIdx.x) >> 5;
    int lane = threadIdx.x & 31;
    if (warp >= NN) return;
    int dst = warp;
    int beg = g_rowstart[dst], end = g_rowstart[dst + 1];
    float4 ad = *(const float4*)(g_ad1 + dst * HEADS);

    int h0 = lane >> 4;                    // head of feature `lane` (0/1); lane+32 -> h0+2
    float acc0 = 0.f, acc1 = 0.f;
    float d0 = 0.f, d1 = 0.f, d2 = 0.f, d3 = 0.f;

    for (int base = beg; base < end; base += 32) {
        int e = base + lane;
        int src = 0;
        float eex = 0.f, eey = 0.f, eez = 0.f, eew = 0.f;
        if (e < end) {
            src = col[e];
            float4 as = *(const float4*)(g_as1 + src * HEADS);
            eex = __expf(leaky(as.x + ad.x));
            eey = __expf(leaky(as.y + ad.y));
            eez = __expf(leaky(as.z + ad.z));
            eew = __expf(leaky(as.w + ad.w));
            d0 += eex; d1 += eey; d2 += eez; d3 += eew;
        }
        int cnt = min(32, end - base);
        for (int j = 0; j < cnt; j++) {
            int   sj = __shfl_sync(0xffffffffu, src, j);
            float e0 = __shfl_sync(0xffffffffu, eex, j);
            float e1 = __shfl_sync(0xffffffffu, eey, j);
            float e2 = __shfl_sync(0xffffffffu, eez, j);
            float e3 = __shfl_sync(0xffffffffu, eew, j);
            float w0 = h0 ? e1 : e0;
            float w1 = h0 ? e3 : e2;
            const float* hrow = g_h1 + sj * HID;
            acc0 = fmaf(hrow[lane],      w0, acc0);
            acc1 = fmaf(hrow[lane + 32], w1, acc1);
        }
    }
#pragma unroll
    for (int off = 16; off; off >>= 1) {
        d0 += __shfl_xor_sync(0xffffffffu, d0, off);
        d1 += __shfl_xor_sync(0xffffffffu, d1, off);
        d2 += __shfl_xor_sync(0xffffffffu, d2, off);
        d3 += __shfl_xor_sync(0xffffffffu, d3, off);
    }
    float dlo = h0 ? d1 : d0;
    float dhi = h0 ? d3 : d2;
    g_agg1[dst * HID + lane]      = acc0 / dlo;
    g_agg1[dst * HID + lane + 32] = acc1 / dhi;
}

// h2 = relu(agg1 + b1) @ W2^T ; alpha2. 8 nodes x 32 outputs per block.
__global__ void gemm2_kernel(const float* __restrict__ W2,
                             const float* __restrict__ b1,
                             const float* __restrict__ a_src,
                             const float* __restrict__ a_dst) {
    __shared__ float Wt[HID * OUT_F];
    __shared__ float xs[8 * HID];
    __shared__ float av[OUT_F], bv[OUT_F], b1s[HID];
    int tid = threadIdx.x;

    for (int i = tid; i < HID * OUT_F; i += 256) {
        int j = i >> 6, k = i & 63;
        Wt[k * OUT_F + j] = W2[j * HID + k];
    }
    if (tid < OUT_F) { av[tid] = a_src[tid]; bv[tid] = a_dst[tid]; }
    if (tid < HID)   b1s[tid] = b1[tid];
    __syncthreads();

    long long base = (long long)blockIdx.x * 8 * HID;
#pragma unroll
    for (int i = tid; i < 8 * HID; i += 256)
        xs[i] = fmaxf(g_agg1[base + i] + b1s[i & 63], 0.f);
    __syncthreads();

    int nl = tid >> 5;
    int j  = tid & 31;
    int node = blockIdx.x * 8 + nl;

    float acc = 0.f;
#pragma unroll
    for (int k = 0; k < HID; k++)
        acc = fmaf(xs[nl * HID + k], Wt[k * OUT_F + j], acc);

    g_h2[node * OUT_F + j] = acc;

    float ps = acc * av[j];
    float pd = acc * bv[j];
#pragma unroll
    for (int off = 16; off; off >>= 1) {
        ps += __shfl_xor_sync(0xffffffffu, ps, off);
        pd += __shfl_xor_sync(0xffffffffu, pd, off);
    }
    if (j == 0) { g_as2[node] = ps; g_ad2[node] = pd; }
}

// fused layer-2 edge softmax + aggregation: warp per dst, 1 head, writes out.
__global__ void fused_agg2(const int* __restrict__ col,
                           const float* __restrict__ b2,
                           float* __restrict__ out) {
    int warp = (blockIdx.x * blockDim.x + threadIdx.x) >> 5;
    int lane = threadIdx.x & 31;
    if (warp >= NN) return;
    int dst = warp;
    int beg = g_rowstart[dst], end = g_rowstart[dst + 1];
    float ad = g_ad2[dst];

    float acc = 0.f, den = 0.f;
    for (int base = beg; base < end; base += 32) {
        int e = base + lane;
        int src = 0;
        float ee = 0.f;
        if (e < end) {
            src = col[e];
            ee = __expf(leaky(g_as2[src] + ad));
            den += ee;
        }
        int cnt = min(32, end - base);
        for (int j = 0; j < cnt; j++) {
            int   sj = __shfl_sync(0xffffffffu, src, j);
            float ej = __shfl_sync(0xffffffffu, ee, j);
            acc = fmaf(g_h2[sj * OUT_F + lane], ej, acc);
        }
    }
#pragma unroll
    for (int off = 16; off; off >>= 1)
        den += __shfl_xor_sync(0xffffffffu, den, off);

    out[dst * OUT_F + lane] = acc / den + b2[lane];
}

// ---------------- launch ----------------
extern "C" void kernel_launch(void* const* d_in, const int* in_sizes, int n_in,
                              void* d_out, int out_size) {
    const float* x      = (const float*)d_in[0];
    const int*   ei     = (const int*)d_in[1];
    const float* W1     = (const float*)d_in[2];
    const float* a_src1 = (const float*)d_in[3];
    const float* a_dst1 = (const float*)d_in[4];
    const float* b1     = (const float*)d_in[5];
    const float* W2     = (const float*)d_in[6];
    const float* a_src2 = (const float*)d_in[7];
    const float* a_dst2 = (const float*)d_in[8];
    const float* b2     = (const float*)d_in[9];
    float* out = (float*)d_out;

    int* d_col;
    cudaGetSymbolAddress((void**)&d_col, g_col);

    const int nodeb = (NN + 255) / 256;
    const int edgeb = (EP + 255) / 256;
    const int warpb = (NN * 32 + 255) / 256;   // warp-per-node kernels

    init_kernel<<<nodeb, 256>>>();
    gemm1_kernel<<<NN / 4, 256>>>(x, W1, a_src1, a_dst1);
    hist_kernel<<<(EE + 255) / 256, 256>>>(ei);
    scan_kernel<<<1, 1024>>>();
    cursor_kernel<<<nodeb, 256>>>();
    scatter_kernel<<<edgeb, 256>>>(ei);
    fused_agg1<<<warpb, 256>>>(d_col);
    gemm2_kernel<<<NN / 8, 256>>>(W2, b1, a_src2, a_dst2);
    fused_agg2<<<warpb, 256>>>(d_col, b2, out);
}

// round 4
// speedup vs baseline: 1.4297x; 1.1635x over previous
#include <cuda_runtime.h>
#include <cuda_bf16.h>
#include <math.h>

#define NN 50000
#define EE 800000
#define EP 850000      // edges + self loops
#define IN_F 64
#define HID 64
#define HEADS 4
#define OUT_F 32
#define NEG_SLOPE 0.2f

#define SCAN_CHUNK 1024
#define NB ((NN + SCAN_CHUNK - 1) / SCAN_CHUNK)   // 49 scan blocks

// ---------------- scratch (static device memory, no allocs) ----------------
__device__ float g_h1[NN * HID];        // layer-1 transformed features
__device__ float g_as1[NN * HEADS];
__device__ float g_ad1[NN * HEADS];
__device__ float g_agg1[NN * HID];      // layer-1 aggregate (pre relu+bias)
__device__ float g_h2[NN * OUT_F];
__device__ float g_as2[NN];
__device__ float g_ad2[NN];
__device__ int   g_deg[NN];             // in-degree (incl self loop)
__device__ int   g_rowstart[NN + 1];    // CSR row offsets (by dst)
__device__ int   g_cur[NN];             // scatter cursors
__device__ int   g_col[EP];             // CSR column (src) indices
__device__ int   g_part[NB];            // per-block partial sums
__device__ int   g_partscan[NB];        // exclusive scan of partials

__device__ __forceinline__ float leaky(float v) {
    return v > 0.f ? v : NEG_SLOPE * v;
}

// ---------------- CSR build ----------------

// init: deg=1 (self loop pre-counted)
__global__ void init_kernel() {
    int i = blockIdx.x * 256 + threadIdx.x;
    if (i < NN) g_deg[i] = 1;
}

// histogram of dst (real edges only)
__global__ void hist_kernel(const int* __restrict__ ei) {
    int e = blockIdx.x * 256 + threadIdx.x;
    if (e < EE) atomicAdd(&g_deg[ei[EE + e]], 1);
}

// Phase A: per-block sums of g_deg (1024 elems / block, 256 threads x 4)
__global__ void scanA_kernel() {
    __shared__ int s[256];
    int tid = threadIdx.x;
    int i0 = blockIdx.x * SCAN_CHUNK + tid * 4;
    int sum = 0;
#pragma unroll
    for (int j = 0; j < 4; j++) {
        int i = i0 + j;
        if (i < NN) sum += g_deg[i];
    }
    s[tid] = sum;
    __syncthreads();
    for (int off = 128; off; off >>= 1) {
        if (tid < off) s[tid] += s[tid + off];
        __syncthreads();
    }
    if (tid == 0) g_part[blockIdx.x] = s[0];
}

// Phase B: scan the NB partials (single 64-thread block)
__global__ void scanB_kernel() {
    __shared__ int s[64];
    int tid = threadIdx.x;
    int v = (tid < NB) ? g_part[tid] : 0;
    s[tid] = v;
    __syncthreads();
    for (int off = 1; off < 64; off <<= 1) {
        int t = (tid >= off) ? s[tid - off] : 0;
        __syncthreads();
        s[tid] += t;
        __syncthreads();
    }
    if (tid < NB) g_partscan[tid] = s[tid] - v;       // exclusive
    if (tid == 63) g_rowstart[NN] = s[63];            // total = EP
}

// Phase C: local exclusive scan, write rowstart[i] and cursor[i]
__global__ void scanC_kernel() {
    __shared__ int s[256];
    int tid = threadIdx.x;
    int i0 = blockIdx.x * SCAN_CHUNK + tid * 4;
    int v[4];
    int sum = 0;
#pragma unroll
    for (int j = 0; j < 4; j++) {
        int i = i0 + j;
        v[j] = (i < NN) ? g_deg[i] : 0;
        sum += v[j];
    }
    s[tid] = sum;
    __syncthreads();
    for (int off = 1; off < 256; off <<= 1) {
        int t = (tid >= off) ? s[tid - off] : 0;
        __syncthreads();
        s[tid] += t;
        __syncthreads();
    }
    int run = g_partscan[blockIdx.x] + s[tid] - sum;  // exclusive prefix at i0
#pragma unroll
    for (int j = 0; j < 4; j++) {
        int i = i0 + j;
        if (i < NN) {
            g_rowstart[i] = run;
            g_cur[i] = run;
            run += v[j];
        }
    }
}

// scatter edges (incl self loops) into CSR buckets by dst
__global__ void scatter_kernel(const int* __restrict__ ei) {
    int e = blockIdx.x * 256 + threadIdx.x;
    if (e >= EP) return;
    int src, dst;
    if (e < EE) { src = ei[e]; dst = ei[EE + e]; }
    else        { src = dst = e - EE; }
    int pos = atomicAdd(&g_cur[dst], 1);
    g_col[pos] = src;
}

// ---------------- layer kernels ----------------

// h1 = x @ W1^T ; alpha_src/dst per node/head. 4 nodes x 64 outputs per block.
__global__ void gemm1_kernel(const float* __restrict__ x,
                             const float* __restrict__ W1,
                             const float* __restrict__ a_src,
                             const float* __restrict__ a_dst) {
    __shared__ float Wt[IN_F * HID];
    __shared__ float xs[4 * IN_F];
    __shared__ float av[HID], bv[HID];
    int tid = threadIdx.x;

    for (int i = tid; i < IN_F * HID; i += 256) {
        int o = i >> 6, k = i & 63;
        Wt[k * HID + o] = W1[o * IN_F + k];
    }
    if (tid < HID) { av[tid] = a_src[tid]; bv[tid] = a_dst[tid]; }
    xs[tid] = x[(long long)blockIdx.x * 4 * IN_F + tid];
    __syncthreads();

    int nl = tid >> 6;
    int o  = tid & 63;
    int node = blockIdx.x * 4 + nl;

    float acc = 0.f;
#pragma unroll
    for (int k = 0; k < IN_F; k++)
        acc = fmaf(xs[nl * IN_F + k], Wt[k * HID + o], acc);

    g_h1[node * HID + o] = acc;

    float ps = acc * av[o];
    float pd = acc * bv[o];
#pragma unroll
    for (int off = 8; off; off >>= 1) {
        ps += __shfl_xor_sync(0xffffffffu, ps, off);
        pd += __shfl_xor_sync(0xffffffffu, pd, off);
    }
    if ((o & 15) == 0) {
        int head = o >> 4;
        g_as1[node * HEADS + head] = ps;
        g_ad1[node * HEADS + head] = pd;
    }
}

// fused layer-1 edge softmax + aggregation: one warp per dst node, no atomics.
__global__ void fused_agg1(const int* __restrict__ col) {
    int warp = (blockIdx.x * blockDim.x + threadIdx.x) >> 5;
    int lane = threadIdx.x & 31;
    if (warp >= NN) return;
    int dst = warp;
    int beg = g_rowstart[dst], end = g_rowstart[dst + 1];
    float4 ad = *(const float4*)(g_ad1 + dst * HEADS);

    int h0 = lane >> 4;                    // head of feature `lane` (0/1)
    float acc0 = 0.f, acc1 = 0.f;
    float d0 = 0.f, d1 = 0.f, d2 = 0.f, d3 = 0.f;

    for (int base = beg; base < end; base += 32) {
        int e = base + lane;
        int src = 0;
        float eex = 0.f, eey = 0.f, eez = 0.f, eew = 0.f;
        if (e < end) {
            src = col[e];
            float4 as = *(const float4*)(g_as1 + src * HEADS);
            eex = __expf(leaky(as.x + ad.x));
            eey = __expf(leaky(as.y + ad.y));
            eez = __expf(leaky(as.z + ad.z));
            eew = __expf(leaky(as.w + ad.w));
            d0 += eex; d1 += eey; d2 += eez; d3 += eew;
        }
        int cnt = min(32, end - base);
        for (int j = 0; j < cnt; j++) {
            int   sj = __shfl_sync(0xffffffffu, src, j);
            float e0 = __shfl_sync(0xffffffffu, eex, j);
            float e1 = __shfl_sync(0xffffffffu, eey, j);
            float e2 = __shfl_sync(0xffffffffu, eez, j);
            float e3 = __shfl_sync(0xffffffffu, eew, j);
            float w0 = h0 ? e1 : e0;
            float w1 = h0 ? e3 : e2;
            const float* hrow = g_h1 + sj * HID;
            acc0 = fmaf(hrow[lane],      w0, acc0);
            acc1 = fmaf(hrow[lane + 32], w1, acc1);
        }
    }
#pragma unroll
    for (int off = 16; off; off >>= 1) {
        d0 += __shfl_xor_sync(0xffffffffu, d0, off);
        d1 += __shfl_xor_sync(0xffffffffu, d1, off);
        d2 += __shfl_xor_sync(0xffffffffu, d2, off);
        d3 += __shfl_xor_sync(0xffffffffu, d3, off);
    }
    float dlo = h0 ? d1 : d0;
    float dhi = h0 ? d3 : d2;
    g_agg1[dst * HID + lane]      = acc0 / dlo;
    g_agg1[dst * HID + lane + 32] = acc1 / dhi;
}

// h2 = relu(agg1 + b1) @ W2^T ; alpha2. 8 nodes x 32 outputs per block.
__global__ void gemm2_kernel(const float* __restrict__ W2,
                             const float* __restrict__ b1,
                             const float* __restrict__ a_src,
                             const float* __restrict__ a_dst) {
    __shared__ float Wt[HID * OUT_F];
    __shared__ float xs[8 * HID];
    __shared__ float av[OUT_F], bv[OUT_F], b1s[HID];
    int tid = threadIdx.x;

    for (int i = tid; i < HID * OUT_F; i += 256) {
        int j = i >> 6, k = i & 63;
        Wt[k * OUT_F + j] = W2[j * HID + k];
    }
    if (tid < OUT_F) { av[tid] = a_src[tid]; bv[tid] = a_dst[tid]; }
    if (tid < HID)   b1s[tid] = b1[tid];
    __syncthreads();

    long long base = (long long)blockIdx.x * 8 * HID;
#pragma unroll
    for (int i = tid; i < 8 * HID; i += 256)
        xs[i] = fmaxf(g_agg1[base + i] + b1s[i & 63], 0.f);
    __syncthreads();

    int nl = tid >> 5;
    int j  = tid & 31;
    int node = blockIdx.x * 8 + nl;

    float acc = 0.f;
#pragma unroll
    for (int k = 0; k < HID; k++)
        acc = fmaf(xs[nl * HID + k], Wt[k * OUT_F + j], acc);

    g_h2[node * OUT_F + j] = acc;

    float ps = acc * av[j];
    float pd = acc * bv[j];
#pragma unroll
    for (int off = 16; off; off >>= 1) {
        ps += __shfl_xor_sync(0xffffffffu, ps, off);
        pd += __shfl_xor_sync(0xffffffffu, pd, off);
    }
    if (j == 0) { g_as2[node] = ps; g_ad2[node] = pd; }
}

// fused layer-2 edge softmax + aggregation: warp per dst, 1 head, writes out.
__global__ void fused_agg2(const int* __restrict__ col,
                           const float* __restrict__ b2,
                           float* __restrict__ out) {
    int warp = (blockIdx.x * blockDim.x + threadIdx.x) >> 5;
    int lane = threadIdx.x & 31;
    if (warp >= NN) return;
    int dst = warp;
    int beg = g_rowstart[dst], end = g_rowstart[dst + 1];
    float ad = g_ad2[dst];

    float acc = 0.f, den = 0.f;
    for (int base = beg; base < end; base += 32) {
        int e = base + lane;
        int src = 0;
        float ee = 0.f;
        if (e < end) {
            src = col[e];
            ee = __expf(leaky(g_as2[src] + ad));
            den += ee;
        }
        int cnt = min(32, end - base);
        for (int j = 0; j < cnt; j++) {
            int   sj = __shfl_sync(0xffffffffu, src, j);
            float ej = __shfl_sync(0xffffffffu, ee, j);
            acc = fmaf(g_h2[sj * OUT_F + lane], ej, acc);
        }
    }
#pragma unroll
    for (int off = 16; off; off >>= 1)
        den += __shfl_xor_sync(0xffffffffu, den, off);

    out[dst * OUT_F + lane] = acc / den + b2[lane];
}

// ---------------- launch ----------------
extern "C" void kernel_launch(void* const* d_in, const int* in_sizes, int n_in,
                              void* d_out, int out_size) {
    const float* x      = (const float*)d_in[0];
    const int*   ei     = (const int*)d_in[1];
    const float* W1     = (const float*)d_in[2];
    const float* a_src1 = (const float*)d_in[3];
    const float* a_dst1 = (const float*)d_in[4];
    const float* b1     = (const float*)d_in[5];
    const float* W2     = (const float*)d_in[6];
    const float* a_src2 = (const float*)d_in[7];
    const float* a_dst2 = (const float*)d_in[8];
    const float* b2     = (const float*)d_in[9];
    float* out = (float*)d_out;

    int* d_col;
    cudaGetSymbolAddress((void**)&d_col, g_col);

    const int nodeb = (NN + 255) / 256;
    const int edgeb = (EP + 255) / 256;
    const int warpb = (NN * 32 + 255) / 256;   // warp-per-node kernels

    init_kernel<<<nodeb, 256>>>();
    gemm1_kernel<<<NN / 4, 256>>>(x, W1, a_src1, a_dst1);
    hist_kernel<<<(EE + 255) / 256, 256>>>(ei);
    scanA_kernel<<<NB, 256>>>();
    scanB_kernel<<<1, 64>>>();
    scanC_kernel<<<NB, 256>>>();
    scatter_kernel<<<edgeb, 256>>>(ei);
    fused_agg1<<<warpb, 256>>>(d_col);
    gemm2_kernel<<<NN / 8, 256>>>(W2, b1, a_src2, a_dst2);
    fused_agg2<<<warpb, 256>>>(d_col, b2, out);
}

// round 5
// speedup vs baseline: 4.0642x; 2.8428x over previous
#include <cuda_runtime.h>
#include <cuda_bf16.h>
#include <math.h>

#define NN 50000
#define EE 800000
#define EP 850000      // edges + self loops
#define IN_F 64
#define HID 64
#define HEADS 4
#define OUT_F 32
#define NEG_SLOPE 0.2f

#define SCAN_CHUNK 1024
#define NB ((NN + SCAN_CHUNK - 1) / SCAN_CHUNK)   // 49 scan blocks

// ---------------- scratch (static device memory, no allocs) ----------------
__device__ float g_W1t[IN_F * HID];     // transposed W1: [k][o]
__device__ float g_W2t[HID * OUT_F];    // transposed W2: [k][j]
__device__ float g_h1[NN * HID];
__device__ float g_as1[NN * HEADS];
__device__ float g_ad1[NN * HEADS];
__device__ float g_agg1[NN * HID];
__device__ float g_h2[NN * OUT_F];
__device__ float g_as2[NN];
__device__ float g_ad2[NN];
__device__ int   g_deg[NN];
__device__ int   g_rowstart[NN + 1];
__device__ int   g_cur[NN];
__device__ int   g_col[EP];
__device__ int   g_part[NB];
__device__ int   g_partscan[NB];

__device__ __forceinline__ float leaky(float v) {
    return v > 0.f ? v : NEG_SLOPE * v;
}

// ---------------- weight transpose (once per call, 1 block) ----------------
__global__ void transpose_kernel(const float* __restrict__ W1,
                                 const float* __restrict__ W2) {
    int tid = threadIdx.x;
    for (int i = tid; i < IN_F * HID; i += 256) {
        int k = i >> 6, o = i & 63;                 // consecutive i -> consecutive write
        g_W1t[k * HID + o] = W1[o * IN_F + k];
    }
    for (int i = tid; i < HID * OUT_F; i += 256) {
        int k = i >> 5, j = i & 31;
        g_W2t[k * OUT_F + j] = W2[j * HID + k];
    }
}

// ---------------- CSR build ----------------
__global__ void init_kernel() {
    int i = blockIdx.x * 256 + threadIdx.x;
    if (i < NN) g_deg[i] = 1;                       // self loop pre-counted
}

__global__ void hist_kernel(const int* __restrict__ ei) {
    int e = blockIdx.x * 256 + threadIdx.x;
    if (e < EE) atomicAdd(&g_deg[ei[EE + e]], 1);
}

__global__ void scanA_kernel() {
    __shared__ int s[256];
    int tid = threadIdx.x;
    int i0 = blockIdx.x * SCAN_CHUNK + tid * 4;
    int sum = 0;
#pragma unroll
    for (int j = 0; j < 4; j++) {
        int i = i0 + j;
        if (i < NN) sum += g_deg[i];
    }
    s[tid] = sum;
    __syncthreads();
    for (int off = 128; off; off >>= 1) {
        if (tid < off) s[tid] += s[tid + off];
        __syncthreads();
    }
    if (tid == 0) g_part[blockIdx.x] = s[0];
}

__global__ void scanB_kernel() {
    __shared__ int s[64];
    int tid = threadIdx.x;
    int v = (tid < NB) ? g_part[tid] : 0;
    s[tid] = v;
    __syncthreads();
    for (int off = 1; off < 64; off <<= 1) {
        int t = (tid >= off) ? s[tid - off] : 0;
        __syncthreads();
        s[tid] += t;
        __syncthreads();
    }
    if (tid < NB) g_partscan[tid] = s[tid] - v;
    if (tid == 63) g_rowstart[NN] = s[63];
}

__global__ void scanC_kernel() {
    __shared__ int s[256];
    int tid = threadIdx.x;
    int i0 = blockIdx.x * SCAN_CHUNK + tid * 4;
    int v[4];
    int sum = 0;
#pragma unroll
    for (int j = 0; j < 4; j++) {
        int i = i0 + j;
        v[j] = (i < NN) ? g_deg[i] : 0;
        sum += v[j];
    }
    s[tid] = sum;
    __syncthreads();
    for (int off = 1; off < 256; off <<= 1) {
        int t = (tid >= off) ? s[tid - off] : 0;
        __syncthreads();
        s[tid] += t;
        __syncthreads();
    }
    int run = g_partscan[blockIdx.x] + s[tid] - sum;
#pragma unroll
    for (int j = 0; j < 4; j++) {
        int i = i0 + j;
        if (i < NN) {
            g_rowstart[i] = run;
            g_cur[i] = run;
            run += v[j];
        }
    }
}

__global__ void scatter_kernel(const int* __restrict__ ei) {
    int e = blockIdx.x * 256 + threadIdx.x;
    if (e >= EP) return;
    int src, dst;
    if (e < EE) { src = ei[e]; dst = ei[EE + e]; }
    else        { src = dst = e - EE; }
    int pos = atomicAdd(&g_cur[dst], 1);
    g_col[pos] = src;
}

// ---------------- gemm1: 64 nodes x 64 outs per block, 4x4 per thread -----
__global__ void gemm1_kernel(const float* __restrict__ x,
                             const float* __restrict__ a_src,
                             const float* __restrict__ a_dst) {
    __shared__ float Wt[IN_F * HID];    // [k][o], conflict-free staging
    __shared__ float xs[64 * 65];       // [n][k], padded stride
    __shared__ float av[HID], bv[HID];
    int tid = threadIdx.x;
    int nbase = blockIdx.x * 64;

    for (int i = tid; i < IN_F * HID; i += 256) Wt[i] = g_W1t[i];
    if (tid < HID) { av[tid] = a_src[tid]; bv[tid] = a_dst[tid]; }
    for (int i = tid; i < 64 * IN_F; i += 256) {
        int n = i >> 6, k = i & 63;
        int node = nbase + n;
        xs[n * 65 + k] = (node < NN) ? x[node * IN_F + k] : 0.f;
    }
    __syncthreads();

    int tx = tid & 15;          // outs 4*tx .. 4*tx+3
    int ty = tid >> 4;          // nodes 4*ty .. 4*ty+3
    float acc[4][4] = {};

#pragma unroll
    for (int k = 0; k < IN_F; k++) {
        float4 w = *(const float4*)&Wt[k * HID + tx * 4];
#pragma unroll
        for (int i = 0; i < 4; i++) {
            float xv = xs[(ty * 4 + i) * 65 + k];
            acc[i][0] = fmaf(xv, w.x, acc[i][0]);
            acc[i][1] = fmaf(xv, w.y, acc[i][1]);
            acc[i][2] = fmaf(xv, w.z, acc[i][2]);
            acc[i][3] = fmaf(xv, w.w, acc[i][3]);
        }
    }

    float a0 = av[tx * 4], a1 = av[tx * 4 + 1], a2 = av[tx * 4 + 2], a3 = av[tx * 4 + 3];
    float c0 = bv[tx * 4], c1 = bv[tx * 4 + 1], c2 = bv[tx * 4 + 2], c3 = bv[tx * 4 + 3];
    int head = tx >> 2;
#pragma unroll
    for (int i = 0; i < 4; i++) {
        int node = nbase + ty * 4 + i;
        float ps = acc[i][0] * a0 + acc[i][1] * a1 + acc[i][2] * a2 + acc[i][3] * a3;
        float pd = acc[i][0] * c0 + acc[i][1] * c1 + acc[i][2] * c2 + acc[i][3] * c3;
        ps += __shfl_xor_sync(0xffffffffu, ps, 1);
        ps += __shfl_xor_sync(0xffffffffu, ps, 2);
        pd += __shfl_xor_sync(0xffffffffu, pd, 1);
        pd += __shfl_xor_sync(0xffffffffu, pd, 2);
        if (node < NN) {
            *(float4*)&g_h1[node * HID + tx * 4] =
                make_float4(acc[i][0], acc[i][1], acc[i][2], acc[i][3]);
            if ((tx & 3) == 0) {
                g_as1[node * HEADS + head] = ps;
                g_ad1[node * HEADS + head] = pd;
            }
        }
    }
}

// ---------------- fused layer-1 softmax+aggregation (warp per dst) --------
__global__ void fused_agg1(const int* __restrict__ col) {
    int warp = (blockIdx.x * blockDim.x + threadIdx.x) >> 5;
    int lane = threadIdx.x & 31;
    if (warp >= NN) return;
    int dst = warp;
    int beg = g_rowstart[dst], end = g_rowstart[dst + 1];
    float4 ad = *(const float4*)(g_ad1 + dst * HEADS);

    int h0 = lane >> 4;
    float acc0 = 0.f, acc1 = 0.f;
    float d0 = 0.f, d1 = 0.f, d2 = 0.f, d3 = 0.f;

    for (int base = beg; base < end; base += 32) {
        int e = base + lane;
        int src = 0;
        float eex = 0.f, eey = 0.f, eez = 0.f, eew = 0.f;
        if (e < end) {
            src = col[e];
            float4 as = *(const float4*)(g_as1 + src * HEADS);
            eex = __expf(leaky(as.x + ad.x));
            eey = __expf(leaky(as.y + ad.y));
            eez = __expf(leaky(as.z + ad.z));
            eew = __expf(leaky(as.w + ad.w));
            d0 += eex; d1 += eey; d2 += eez; d3 += eew;
        }
        int cnt = min(32, end - base);
        for (int j = 0; j < cnt; j++) {
            int   sj = __shfl_sync(0xffffffffu, src, j);
            float e0 = __shfl_sync(0xffffffffu, eex, j);
            float e1 = __shfl_sync(0xffffffffu, eey, j);
            float e2 = __shfl_sync(0xffffffffu, eez, j);
            float e3 = __shfl_sync(0xffffffffu, eew, j);
            float w0 = h0 ? e1 : e0;
            float w1 = h0 ? e3 : e2;
            const float* hrow = g_h1 + sj * HID;
            acc0 = fmaf(hrow[lane],      w0, acc0);
            acc1 = fmaf(hrow[lane + 32], w1, acc1);
        }
    }
#pragma unroll
    for (int off = 16; off; off >>= 1) {
        d0 += __shfl_xor_sync(0xffffffffu, d0, off);
        d1 += __shfl_xor_sync(0xffffffffu, d1, off);
        d2 += __shfl_xor_sync(0xffffffffu, d2, off);
        d3 += __shfl_xor_sync(0xffffffffu, d3, off);
    }
    float dlo = h0 ? d1 : d0;
    float dhi = h0 ? d3 : d2;
    g_agg1[dst * HID + lane]      = acc0 / dlo;
    g_agg1[dst * HID + lane + 32] = acc1 / dhi;
}

// ---------------- gemm2: 128 nodes x 32 outs per block, 4x4 per thread ----
__global__ void gemm2_kernel(const float* __restrict__ b1,
                             const float* __restrict__ a_src,
                             const float* __restrict__ a_dst) {
    __shared__ float Wt[HID * OUT_F];   // [k][j]
    __shared__ float xs[128 * 65];      // [n][k] relu(agg1+b1), padded
    __shared__ float av[OUT_F], bv[OUT_F];
    int tid = threadIdx.x;
    int nbase = blockIdx.x * 128;

    for (int i = tid; i < HID * OUT_F; i += 256) Wt[i] = g_W2t[i];
    if (tid < OUT_F) { av[tid] = a_src[tid]; bv[tid] = a_dst[tid]; }
    for (int i = tid; i < 128 * HID; i += 256) {
        int n = i >> 6, k = i & 63;
        int node = nbase + n;
        xs[n * 65 + k] = (node < NN)
            ? fmaxf(g_agg1[node * HID + k] + __ldg(&b1[k]), 0.f) : 0.f;
    }
    __syncthreads();

    int tx = tid & 7;           // outs 4*tx .. 4*tx+3
    int ty = tid >> 3;          // nodes 4*ty .. 4*ty+3
    float acc[4][4] = {};

#pragma unroll
    for (int k = 0; k < HID; k++) {
        float4 w = *(const float4*)&Wt[k * OUT_F + tx * 4];
#pragma unroll
        for (int i = 0; i < 4; i++) {
            float xv = xs[(ty * 4 + i) * 65 + k];
            acc[i][0] = fmaf(xv, w.x, acc[i][0]);
            acc[i][1] = fmaf(xv, w.y, acc[i][1]);
            acc[i][2] = fmaf(xv, w.z, acc[i][2]);
            acc[i][3] = fmaf(xv, w.w, acc[i][3]);
        }
    }

    float a0 = av[tx * 4], a1 = av[tx * 4 + 1], a2 = av[tx * 4 + 2], a3 = av[tx * 4 + 3];
    float c0 = bv[tx * 4], c1 = bv[tx * 4 + 1], c2 = bv[tx * 4 + 2], c3 = bv[tx * 4 + 3];
#pragma unroll
    for (int i = 0; i < 4; i++) {
        int node = nbase + ty * 4 + i;
        float ps = acc[i][0] * a0 + acc[i][1] * a1 + acc[i][2] * a2 + acc[i][3] * a3;
        float pd = acc[i][0] * c0 + acc[i][1] * c1 + acc[i][2] * c2 + acc[i][3] * c3;
        ps += __shfl_xor_sync(0xffffffffu, ps, 1);
        ps += __shfl_xor_sync(0xffffffffu, ps, 2);
        ps += __shfl_xor_sync(0xffffffffu, ps, 4);
        pd += __shfl_xor_sync(0xffffffffu, pd, 1);
        pd += __shfl_xor_sync(0xffffffffu, pd, 2);
        pd += __shfl_xor_sync(0xffffffffu, pd, 4);
        if (node < NN) {
            *(float4*)&g_h2[node * OUT_F + tx * 4] =
                make_float4(acc[i][0], acc[i][1], acc[i][2], acc[i][3]);
            if (tx == 0) { g_as2[node] = ps; g_ad2[node] = pd; }
        }
    }
}

// ---------------- fused layer-2 softmax+aggregation (warp per dst) --------
__global__ void fused_agg2(const int* __restrict__ col,
                           const float* __restrict__ b2,
                           float* __restrict__ out) {
    int warp = (blockIdx.x * blockDim.x + threadIdx.x) >> 5;
    int lane = threadIdx.x & 31;
    if (warp >= NN) return;
    int dst = warp;
    int beg = g_rowstart[dst], end = g_rowstart[dst + 1];
    float ad = g_ad2[dst];

    float acc = 0.f, den = 0.f;
    for (int base = beg; base < end; base += 32) {
        int e = base + lane;
        int src = 0;
        float ee = 0.f;
        if (e < end) {
            src = col[e];
            ee = __expf(leaky(g_as2[src] + ad));
            den += ee;
        }
        int cnt = min(32, end - base);
        for (int j = 0; j < cnt; j++) {
            int   sj = __shfl_sync(0xffffffffu, src, j);
            float ej = __shfl_sync(0xffffffffu, ee, j);
            acc = fmaf(g_h2[sj * OUT_F + lane], ej, acc);
        }
    }
#pragma unroll
    for (int off = 16; off; off >>= 1)
        den += __shfl_xor_sync(0xffffffffu, den, off);

    out[dst * OUT_F + lane] = acc / den + b2[lane];
}

// ---------------- launch ----------------
extern "C" void kernel_launch(void* const* d_in, const int* in_sizes, int n_in,
                              void* d_out, int out_size) {
    const float* x      = (const float*)d_in[0];
    const int*   ei     = (const int*)d_in[1];
    const float* W1     = (const float*)d_in[2];
    const float* a_src1 = (const float*)d_in[3];
    const float* a_dst1 = (const float*)d_in[4];
    const float* b1     = (const float*)d_in[5];
    const float* W2     = (const float*)d_in[6];
    const float* a_src2 = (const float*)d_in[7];
    const float* a_dst2 = (const float*)d_in[8];
    const float* b2     = (const float*)d_in[9];
    float* out = (float*)d_out;

    int* d_col;
    cudaGetSymbolAddress((void**)&d_col, g_col);

    const int nodeb = (NN + 255) / 256;
    const int edgeb = (EP + 255) / 256;
    const int warpb = (NN * 32 + 255) / 256;

    transpose_kernel<<<1, 256>>>(W1, W2);                    // 1
    init_kernel<<<nodeb, 256>>>();                           // 2
    hist_kernel<<<(EE + 255) / 256, 256>>>(ei);              // 3
    gemm1_kernel<<<(NN + 63) / 64, 256>>>(x, a_src1, a_dst1);// 4  <- profiled slot
    scanA_kernel<<<NB, 256>>>();                             // 5
    scanB_kernel<<<1, 64>>>();                               // 6
    scanC_kernel<<<NB, 256>>>();                             // 7
    scatter_kernel<<<edgeb, 256>>>(ei);                      // 8
    fused_agg1<<<warpb, 256>>>(d_col);                       // 9
    gemm2_kernel<<<(NN + 127) / 128, 256>>>(b1, a_src2, a_dst2); // 10
    fused_agg2<<<warpb, 256>>>(d_col, b2, out);              // 11
}

// round 6
// speedup vs baseline: 4.4010x; 1.0829x over previous
#include <cuda_runtime.h>
#include <cuda_bf16.h>
#include <cuda_fp16.h>
#include <math.h>

#define NN 50000
#define EE 800000
#define EP 850000      // edges + self loops
#define IN_F 64
#define HID 64
#define HEADS 4
#define OUT_F 32
#define NEG_SLOPE 0.2f

#define SCAN_CHUNK 1024
#define NB ((NN + SCAN_CHUNK - 1) / SCAN_CHUNK)   // 49 scan blocks

// ---------------- scratch (static device memory, no allocs) ----------------
__device__ float  g_W1t[IN_F * HID];    // transposed W1: [k][o]
__device__ float  g_W2t[HID * OUT_F];   // transposed W2: [k][j]
__device__ __half2 g_h1h[NN * 32];      // layer-1 features, fp16: pair (2l,2l+1)
__device__ __half  g_h2h[NN * OUT_F];   // layer-2 features, fp16
__device__ float  g_as1[NN * HEADS];
__device__ float  g_ad1[NN * HEADS];
__device__ float  g_agg1[NN * HID];
__device__ float  g_as2[NN];
__device__ float  g_ad2[NN];
__device__ int    g_deg[NN];
__device__ int    g_rowstart[NN + 1];
__device__ int    g_cur[NN];
__device__ int    g_col[EP];
__device__ int    g_part[NB];
__device__ int    g_partscan[NB];

__device__ __forceinline__ float leaky(float v) {
    return v > 0.f ? v : NEG_SLOPE * v;
}

// ---------------- weight transpose (once per call, 1 block) ----------------
__global__ void transpose_kernel(const float* __restrict__ W1,
                                 const float* __restrict__ W2) {
    int tid = threadIdx.x;
    for (int i = tid; i < IN_F * HID; i += 256) {
        int k = i >> 6, o = i & 63;
        g_W1t[k * HID + o] = W1[o * IN_F + k];
    }
    for (int i = tid; i < HID * OUT_F; i += 256) {
        int k = i >> 5, j = i & 31;
        g_W2t[k * OUT_F + j] = W2[j * HID + k];
    }
}

// ---------------- CSR build ----------------
__global__ void init_kernel() {
    int i = blockIdx.x * 256 + threadIdx.x;
    if (i < NN) g_deg[i] = 1;                       // self loop pre-counted
}

__global__ void hist_kernel(const int* __restrict__ ei) {
    int e = blockIdx.x * 256 + threadIdx.x;
    if (e < EE) atomicAdd(&g_deg[ei[EE + e]], 1);
}

__global__ void scanA_kernel() {
    __shared__ int s[256];
    int tid = threadIdx.x;
    int i0 = blockIdx.x * SCAN_CHUNK + tid * 4;
    int sum = 0;
#pragma unroll
    for (int j = 0; j < 4; j++) {
        int i = i0 + j;
        if (i < NN) sum += g_deg[i];
    }
    s[tid] = sum;
    __syncthreads();
    for (int off = 128; off; off >>= 1) {
        if (tid < off) s[tid] += s[tid + off];
        __syncthreads();
    }
    if (tid == 0) g_part[blockIdx.x] = s[0];
}

__global__ void scanB_kernel() {
    __shared__ int s[64];
    int tid = threadIdx.x;
    int v = (tid < NB) ? g_part[tid] : 0;
    s[tid] = v;
    __syncthreads();
    for (int off = 1; off < 64; off <<= 1) {
        int t = (tid >= off) ? s[tid - off] : 0;
        __syncthreads();
        s[tid] += t;
        __syncthreads();
    }
    if (tid < NB) g_partscan[tid] = s[tid] - v;
    if (tid == 63) g_rowstart[NN] = s[63];
}

__global__ void scanC_kernel() {
    __shared__ int s[256];
    int tid = threadIdx.x;
    int i0 = blockIdx.x * SCAN_CHUNK + tid * 4;
    int v[4];
    int sum = 0;
#pragma unroll
    for (int j = 0; j < 4; j++) {
        int i = i0 + j;
        v[j] = (i < NN) ? g_deg[i] : 0;
        sum += v[j];
    }
    s[tid] = sum;
    __syncthreads();
    for (int off = 1; off < 256; off <<= 1) {
        int t = (tid >= off) ? s[tid - off] : 0;
        __syncthreads();
        s[tid] += t;
        __syncthreads();
    }
    int run = g_partscan[blockIdx.x] + s[tid] - sum;
#pragma unroll
    for (int j = 0; j < 4; j++) {
        int i = i0 + j;
        if (i < NN) {
            g_rowstart[i] = run;
            g_cur[i] = run;
            run += v[j];
        }
    }
}

__global__ void scatter_kernel(const int* __restrict__ ei) {
    int e = blockIdx.x * 256 + threadIdx.x;
    if (e >= EP) return;
    int src, dst;
    if (e < EE) { src = ei[e]; dst = ei[EE + e]; }
    else        { src = dst = e - EE; }
    int pos = atomicAdd(&g_cur[dst], 1);
    g_col[pos] = src;
}

// ---- gemm1: 64 nodes x 64 outs per block (128 thr), 8n x 4o per thread ----
__global__ void gemm1_kernel(const float* __restrict__ x,
                             const float* __restrict__ a_src,
                             const float* __restrict__ a_dst) {
    __shared__ float Wt[IN_F * HID];    // [k][o]
    __shared__ float xs[64 * 65];       // [n][k], padded stride
    __shared__ float av[HID], bv[HID];
    int tid = threadIdx.x;
    int nbase = blockIdx.x * 64;

    for (int i = tid; i < IN_F * HID; i += 128) Wt[i] = g_W1t[i];
    if (tid < HID) { av[tid] = a_src[tid]; bv[tid] = a_dst[tid]; }
    for (int i = tid; i < 64 * IN_F; i += 128) {
        int n = i >> 6, k = i & 63;
        int node = nbase + n;
        xs[n * 65 + k] = (node < NN) ? x[node * IN_F + k] : 0.f;
    }
    __syncthreads();

    int tx = tid & 15;          // outs 4*tx .. 4*tx+3
    int ty = tid >> 4;          // nodes 8*ty .. 8*ty+7
    float acc[8][4] = {};

#pragma unroll 8
    for (int k = 0; k < IN_F; k++) {
        float4 w = *(const float4*)&Wt[k * HID + tx * 4];
#pragma unroll
        for (int i = 0; i < 8; i++) {
            float xv = xs[(ty * 8 + i) * 65 + k];
            acc[i][0] = fmaf(xv, w.x, acc[i][0]);
            acc[i][1] = fmaf(xv, w.y, acc[i][1]);
            acc[i][2] = fmaf(xv, w.z, acc[i][2]);
            acc[i][3] = fmaf(xv, w.w, acc[i][3]);
        }
    }

    float a0 = av[tx * 4], a1 = av[tx * 4 + 1], a2 = av[tx * 4 + 2], a3 = av[tx * 4 + 3];
    float c0 = bv[tx * 4], c1 = bv[tx * 4 + 1], c2 = bv[tx * 4 + 2], c3 = bv[tx * 4 + 3];
    int head = tx >> 2;
#pragma unroll
    for (int i = 0; i < 8; i++) {
        int node = nbase + ty * 8 + i;
        float ps = acc[i][0] * a0 + acc[i][1] * a1 + acc[i][2] * a2 + acc[i][3] * a3;
        float pd = acc[i][0] * c0 + acc[i][1] * c1 + acc[i][2] * c2 + acc[i][3] * c3;
        ps += __shfl_xor_sync(0xffffffffu, ps, 1);
        ps += __shfl_xor_sync(0xffffffffu, ps, 2);
        pd += __shfl_xor_sync(0xffffffffu, pd, 1);
        pd += __shfl_xor_sync(0xffffffffu, pd, 2);
        if (node < NN) {
            __half2 p0 = __floats2half2_rn(acc[i][0], acc[i][1]);
            __half2 p1 = __floats2half2_rn(acc[i][2], acc[i][3]);
            uint2 u;
            u.x = *(unsigned int*)&p0;
            u.y = *(unsigned int*)&p1;
            *(uint2*)&g_h1h[node * 32 + tx * 2] = u;   // halves 4tx..4tx+3
            if ((tx & 3) == 0) {
                g_as1[node * HEADS + head] = ps;
                g_ad1[node * HEADS + head] = pd;
            }
        }
    }
}

// ---- fused layer-1 softmax+aggregation (warp per dst), fp16 gathers ------
// lane owns features (2*lane, 2*lane+1); both are in head = lane>>3.
__global__ void fused_agg1(const int* __restrict__ col) {
    int warp = (blockIdx.x * blockDim.x + threadIdx.x) >> 5;
    int lane = threadIdx.x & 31;
    if (warp >= NN) return;
    int dst = warp;
    int beg = g_rowstart[dst], end = g_rowstart[dst + 1];
    float4 ad = *(const float4*)(g_ad1 + dst * HEADS);
    int head = lane >> 3;

    float acc0 = 0.f, acc1 = 0.f;
    float d0 = 0.f, d1 = 0.f, d2 = 0.f, d3 = 0.f;

    for (int base = beg; base < end; base += 32) {
        int e = base + lane;
        int src = 0;
        float eex = 0.f, eey = 0.f, eez = 0.f, eew = 0.f;
        if (e < end) {
            src = col[e];
            float4 as = *(const float4*)(g_as1 + src * HEADS);
            eex = __expf(leaky(as.x + ad.x));
            eey = __expf(leaky(as.y + ad.y));
            eez = __expf(leaky(as.z + ad.z));
            eew = __expf(leaky(as.w + ad.w));
            d0 += eex; d1 += eey; d2 += eez; d3 += eew;
        }
        int cnt = min(32, end - base);
        for (int j = 0; j < cnt; j++) {
            int   sj = __shfl_sync(0xffffffffu, src, j);
            float e0 = __shfl_sync(0xffffffffu, eex, j);
            float e1 = __shfl_sync(0xffffffffu, eey, j);
            float e2 = __shfl_sync(0xffffffffu, eez, j);
            float e3 = __shfl_sync(0xffffffffu, eew, j);
            float w = (head & 2) ? ((head & 1) ? e3 : e2)
                                 : ((head & 1) ? e1 : e0);
            float2 f = __half22float2(g_h1h[sj * 32 + lane]);
            acc0 = fmaf(f.x, w, acc0);
            acc1 = fmaf(f.y, w, acc1);
        }
    }
#pragma unroll
    for (int off = 16; off; off >>= 1) {
        d0 += __shfl_xor_sync(0xffffffffu, d0, off);
        d1 += __shfl_xor_sync(0xffffffffu, d1, off);
        d2 += __shfl_xor_sync(0xffffffffu, d2, off);
        d3 += __shfl_xor_sync(0xffffffffu, d3, off);
    }
    float dd = (head & 2) ? ((head & 1) ? d3 : d2)
                          : ((head & 1) ? d1 : d0);
    *(float2*)&g_agg1[dst * HID + lane * 2] = make_float2(acc0 / dd, acc1 / dd);
}

// ---- gemm2: 128 nodes x 32 outs per block, 4x4 per thread ----------------
__global__ void gemm2_kernel(const float* __restrict__ b1,
                             const float* __restrict__ a_src,
                             const float* __restrict__ a_dst) {
    __shared__ float Wt[HID * OUT_F];   // [k][j]
    __shared__ float xs[128 * 65];      // [n][k] relu(agg1+b1), padded
    __shared__ float av[OUT_F], bv[OUT_F];
    int tid = threadIdx.x;
    int nbase = blockIdx.x * 128;

    for (int i = tid; i < HID * OUT_F; i += 256) Wt[i] = g_W2t[i];
    if (tid < OUT_F) { av[tid] = a_src[tid]; bv[tid] = a_dst[tid]; }
    for (int i = tid; i < 128 * HID; i += 256) {
        int n = i >> 6, k = i & 63;
        int node = nbase + n;
        xs[n * 65 + k] = (node < NN)
            ? fmaxf(g_agg1[node * HID + k] + __ldg(&b1[k]), 0.f) : 0.f;
    }
    __syncthreads();

    int tx = tid & 7;           // outs 4*tx .. 4*tx+3
    int ty = tid >> 3;          // nodes 4*ty .. 4*ty+3
    float acc[4][4] = {};

#pragma unroll 8
    for (int k = 0; k < HID; k++) {
        float4 w = *(const float4*)&Wt[k * OUT_F + tx * 4];
#pragma unroll
        for (int i = 0; i < 4; i++) {
            float xv = xs[(ty * 4 + i) * 65 + k];
            acc[i][0] = fmaf(xv, w.x, acc[i][0]);
            acc[i][1] = fmaf(xv, w.y, acc[i][1]);
            acc[i][2] = fmaf(xv, w.z, acc[i][2]);
            acc[i][3] = fmaf(xv, w.w, acc[i][3]);
        }
    }

    float a0 = av[tx * 4], a1 = av[tx * 4 + 1], a2 = av[tx * 4 + 2], a3 = av[tx * 4 + 3];
    float c0 = bv[tx * 4], c1 = bv[tx * 4 + 1], c2 = bv[tx * 4 + 2], c3 = bv[tx * 4 + 3];
#pragma unroll
    for (int i = 0; i < 4; i++) {
        int node = nbase + ty * 4 + i;
        float ps = acc[i][0] * a0 + acc[i][1] * a1 + acc[i][2] * a2 + acc[i][3] * a3;
        float pd = acc[i][0] * c0 + acc[i][1] * c1 + acc[i][2] * c2 + acc[i][3] * c3;
        ps += __shfl_xor_sync(0xffffffffu, ps, 1);
        ps += __shfl_xor_sync(0xffffffffu, ps, 2);
        ps += __shfl_xor_sync(0xffffffffu, ps, 4);
        pd += __shfl_xor_sync(0xffffffffu, pd, 1);
        pd += __shfl_xor_sync(0xffffffffu, pd, 2);
        pd += __shfl_xor_sync(0xffffffffu, pd, 4);
        if (node < NN) {
            __half2 p0 = __floats2half2_rn(acc[i][0], acc[i][1]);
            __half2 p1 = __floats2half2_rn(acc[i][2], acc[i][3]);
            uint2 u;
            u.x = *(unsigned int*)&p0;
            u.y = *(unsigned int*)&p1;
            *(uint2*)&g_h2h[node * OUT_F + tx * 4] = u;
            if (tx == 0) { g_as2[node] = ps; g_ad2[node] = pd; }
        }
    }
}

// ---- fused layer-2 softmax+aggregation (warp per dst), fp16 gathers ------
__global__ void fused_agg2(const int* __restrict__ col,
                           const float* __restrict__ b2,
                           float* __restrict__ out) {
    int warp = (blockIdx.x * blockDim.x + threadIdx.x) >> 5;
    int lane = threadIdx.x & 31;
    if (warp >= NN) return;
    int dst = warp;
    int beg = g_rowstart[dst], end = g_rowstart[dst + 1];
    float ad = g_ad2[dst];

    float acc = 0.f, den = 0.f;
    for (int base = beg; base < end; base += 32) {
        int e = base + lane;
        int src = 0;
        float ee = 0.f;
        if (e < end) {
            src = col[e];
            ee = __expf(leaky(g_as2[src] + ad));
            den += ee;
        }
        int cnt = min(32, end - base);
        for (int j = 0; j < cnt; j++) {
            int   sj = __shfl_sync(0xffffffffu, src, j);
            float ej = __shfl_sync(0xffffffffu, ee, j);
            acc = fmaf(__half2float(g_h2h[sj * OUT_F + lane]), ej, acc);
        }
    }
#pragma unroll
    for (int off = 16; off; off >>= 1)
        den += __shfl_xor_sync(0xffffffffu, den, off);

    out[dst * OUT_F + lane] = acc / den + b2[lane];
}

// ---------------- launch ----------------
extern "C" void kernel_launch(void* const* d_in, const int* in_sizes, int n_in,
                              void* d_out, int out_size) {
    const float* x      = (const float*)d_in[0];
    const int*   ei     = (const int*)d_in[1];
    const float* W1     = (const float*)d_in[2];
    const float* a_src1 = (const float*)d_in[3];
    const float* a_dst1 = (const float*)d_in[4];
    const float* b1     = (const float*)d_in[5];
    const float* W2     = (const float*)d_in[6];
    const float* a_src2 = (const float*)d_in[7];
    const float* a_dst2 = (const float*)d_in[8];
    const float* b2     = (const float*)d_in[9];
    float* out = (float*)d_out;

    int* d_col;
    cudaGetSymbolAddress((void**)&d_col, g_col);

    const int nodeb = (NN + 255) / 256;
    const int edgeb = (EP + 255) / 256;
    const int warpb = (NN * 32 + 255) / 256;

    transpose_kernel<<<1, 256>>>(W1, W2);                        // 1
    init_kernel<<<nodeb, 256>>>();                               // 2
    hist_kernel<<<(EE + 255) / 256, 256>>>(ei);                  // 3
    gemm1_kernel<<<(NN + 63) / 64, 128>>>(x, a_src1, a_dst1);    // 4  <- profiled slot
    scanA_kernel<<<NB, 256>>>();                                 // 5
    scanB_kernel<<<1, 64>>>();                                   // 6
    scanC_kernel<<<NB, 256>>>();                                 // 7
    scatter_kernel<<<edgeb, 256>>>(ei);                          // 8
    fused_agg1<<<warpb, 256>>>(d_col);                           // 9
    gemm2_kernel<<<(NN + 127) / 128, 256>>>(b1, a_src2, a_dst2); // 10
    fused_agg2<<<warpb, 256>>>(d_col, b2, out);                  // 11
}

// round 7
// speedup vs baseline: 4.5370x; 1.0309x over previous
#include <cuda_runtime.h>
#include <cuda_bf16.h>
#include <cuda_fp16.h>
#include <math.h>

#define NN 50000
#define EE 800000
#define EP 850000      // edges + self loops
#define IN_F 64
#define HID 64
#define HEADS 4
#define OUT_F 32
#define NEG_SLOPE 0.2f

#define SCAN_CHUNK 1024
#define NB ((NN + SCAN_CHUNK - 1) / SCAN_CHUNK)   // 49 scan blocks

// ---------------- scratch (static device memory, no allocs) ----------------
__device__ float   g_W1t[IN_F * HID];    // transposed W1: [k][o]
__device__ float   g_W2t[HID * OUT_F];   // transposed W2: [k][j]
__device__ __half2 g_h1h[NN * 32];       // layer-1 features: pair (2l,2l+1)
__device__ __half2 g_h2h[NN * 16];       // layer-2 features: pair (2f,2f+1)
__device__ float   g_as1[NN * HEADS];
__device__ float   g_ad1[NN * HEADS];
__device__ float   g_agg1[NN * HID];
__device__ float   g_as2[NN];
__device__ float   g_ad2[NN];
__device__ int     g_deg[NN];
__device__ int     g_rowstart[NN + 1];
__device__ int     g_cur[NN];
__device__ int     g_col[EP];
__device__ int     g_part[NB];
__device__ int     g_partscan[NB];

__device__ __forceinline__ float leaky(float v) {
    return v > 0.f ? v : NEG_SLOPE * v;
}

// ---------------- init + weight transpose (merged) ------------------------
__global__ void init_kernel(const float* __restrict__ W1,
                            const float* __restrict__ W2) {
    int i = blockIdx.x * 256 + threadIdx.x;
    if (i < NN) g_deg[i] = 1;                       // self loop pre-counted
    if (blockIdx.x == 0) {                          // block 0 also transposes
        int tid = threadIdx.x;
        for (int p = tid; p < IN_F * HID; p += 256) {
            int k = p >> 6, o = p & 63;
            g_W1t[k * HID + o] = W1[o * IN_F + k];
        }
        for (int p = tid; p < HID * OUT_F; p += 256) {
            int k = p >> 5, j = p & 31;
            g_W2t[k * OUT_F + j] = W2[j * HID + k];
        }
    }
}

// ---------------- CSR build ----------------
__global__ void hist_kernel(const int* __restrict__ ei) {
    int e = blockIdx.x * 256 + threadIdx.x;
    if (e < EE) atomicAdd(&g_deg[ei[EE + e]], 1);
}

__global__ void scanA_kernel() {
    __shared__ int s[256];
    int tid = threadIdx.x;
    int i0 = blockIdx.x * SCAN_CHUNK + tid * 4;
    int sum = 0;
#pragma unroll
    for (int j = 0; j < 4; j++) {
        int i = i0 + j;
        if (i < NN) sum += g_deg[i];
    }
    s[tid] = sum;
    __syncthreads();
    for (int off = 128; off; off >>= 1) {
        if (tid < off) s[tid] += s[tid + off];
        __syncthreads();
    }
    if (tid == 0) g_part[blockIdx.x] = s[0];
}

__global__ void scanB_kernel() {
    __shared__ int s[64];
    int tid = threadIdx.x;
    int v = (tid < NB) ? g_part[tid] : 0;
    s[tid] = v;
    __syncthreads();
    for (int off = 1; off < 64; off <<= 1) {
        int t = (tid >= off) ? s[tid - off] : 0;
        __syncthreads();
        s[tid] += t;
        __syncthreads();
    }
    if (tid < NB) g_partscan[tid] = s[tid] - v;
    if (tid == 63) g_rowstart[NN] = s[63];
}

__global__ void scanC_kernel() {
    __shared__ int s[256];
    int tid = threadIdx.x;
    int i0 = blockIdx.x * SCAN_CHUNK + tid * 4;
    int v[4];
    int sum = 0;
#pragma unroll
    for (int j = 0; j < 4; j++) {
        int i = i0 + j;
        v[j] = (i < NN) ? g_deg[i] : 0;
        sum += v[j];
    }
    s[tid] = sum;
    __syncthreads();
    for (int off = 1; off < 256; off <<= 1) {
        int t = (tid >= off) ? s[tid - off] : 0;
        __syncthreads();
        s[tid] += t;
        __syncthreads();
    }
    int run = g_partscan[blockIdx.x] + s[tid] - sum;
#pragma unroll
    for (int j = 0; j < 4; j++) {
        int i = i0 + j;
        if (i < NN) {
            g_rowstart[i] = run;
            g_cur[i] = run;
            run += v[j];
        }
    }
}

__global__ void scatter_kernel(const int* __restrict__ ei) {
    int e = blockIdx.x * 256 + threadIdx.x;
    if (e >= EP) return;
    int src, dst;
    if (e < EE) { src = ei[e]; dst = ei[EE + e]; }
    else        { src = dst = e - EE; }
    int pos = atomicAdd(&g_cur[dst], 1);
    g_col[pos] = src;
}

// ---- gemm1: 64 nodes x 64 outs per block (128 thr), 8n x 4o per thread ----
__global__ void gemm1_kernel(const float* __restrict__ x,
                             const float* __restrict__ a_src,
                             const float* __restrict__ a_dst) {
    __shared__ float Wt[IN_F * HID];    // [k][o]
    __shared__ float xs[64 * 68];       // [n][k], padded stride (16B aligned)
    __shared__ float av[HID], bv[HID];
    int tid = threadIdx.x;
    int nbase = blockIdx.x * 64;

    for (int i = tid; i < IN_F * HID; i += 128) Wt[i] = g_W1t[i];
    if (tid < HID) { av[tid] = a_src[tid]; bv[tid] = a_dst[tid]; }
    for (int i = tid; i < 64 * IN_F; i += 128) {
        int n = i >> 6, k = i & 63;
        int node = nbase + n;
        xs[n * 68 + k] = (node < NN) ? x[node * IN_F + k] : 0.f;
    }
    __syncthreads();

    int tx = tid & 15;          // outs 4*tx .. 4*tx+3
    int ty = tid >> 4;          // nodes 8*ty .. 8*ty+7
    float acc[8][4] = {};

#pragma unroll 4
    for (int k4 = 0; k4 < IN_F; k4 += 4) {
        float4 xv[8];
#pragma unroll
        for (int i = 0; i < 8; i++)
            xv[i] = *(const float4*)&xs[(ty * 8 + i) * 68 + k4];
#pragma unroll
        for (int kk = 0; kk < 4; kk++) {
            float4 w = *(const float4*)&Wt[(k4 + kk) * HID + tx * 4];
#pragma unroll
            for (int i = 0; i < 8; i++) {
                float xvk = (kk == 0) ? xv[i].x : (kk == 1) ? xv[i].y
                          : (kk == 2) ? xv[i].z : xv[i].w;
                acc[i][0] = fmaf(xvk, w.x, acc[i][0]);
                acc[i][1] = fmaf(xvk, w.y, acc[i][1]);
                acc[i][2] = fmaf(xvk, w.z, acc[i][2]);
                acc[i][3] = fmaf(xvk, w.w, acc[i][3]);
            }
        }
    }

    float a0 = av[tx * 4], a1 = av[tx * 4 + 1], a2 = av[tx * 4 + 2], a3 = av[tx * 4 + 3];
    float c0 = bv[tx * 4], c1 = bv[tx * 4 + 1], c2 = bv[tx * 4 + 2], c3 = bv[tx * 4 + 3];
    int head = tx >> 2;
#pragma unroll
    for (int i = 0; i < 8; i++) {
        int node = nbase + ty * 8 + i;
        float ps = acc[i][0] * a0 + acc[i][1] * a1 + acc[i][2] * a2 + acc[i][3] * a3;
        float pd = acc[i][0] * c0 + acc[i][1] * c1 + acc[i][2] * c2 + acc[i][3] * c3;
        ps += __shfl_xor_sync(0xffffffffu, ps, 1);
        ps += __shfl_xor_sync(0xffffffffu, ps, 2);
        pd += __shfl_xor_sync(0xffffffffu, pd, 1);
        pd += __shfl_xor_sync(0xffffffffu, pd, 2);
        if (node < NN) {
            __half2 p0 = __floats2half2_rn(acc[i][0], acc[i][1]);
            __half2 p1 = __floats2half2_rn(acc[i][2], acc[i][3]);
            uint2 u;
            u.x = *(unsigned int*)&p0;
            u.y = *(unsigned int*)&p1;
            *(uint2*)&g_h1h[node * 32 + tx * 2] = u;
            if ((tx & 3) == 0) {
                g_as1[node * HEADS + head] = ps;
                g_ad1[node * HEADS + head] = pd;
            }
        }
    }
}

// ---- fused layer-1 softmax+aggregation (warp per dst) --------------------
// lane = head*8 + slot. Per 8-edge round each lane computes ONE exp
// (its head, its slot). Features: lane owns (2*lane, 2*lane+1), whose head
// is lane>>3 == head. Denominator reduced within aligned 8-lane head groups.
__global__ void fused_agg1(const int* __restrict__ col) {
    int warp = (blockIdx.x * blockDim.x + threadIdx.x) >> 5;
    int lane = threadIdx.x & 31;
    if (warp >= NN) return;
    int dst = warp;
    int beg = g_rowstart[dst], end = g_rowstart[dst + 1];
    int head = lane >> 3;
    int slot = lane & 7;
    float adh = g_ad1[dst * HEADS + head];

    float acc0 = 0.f, acc1 = 0.f, den = 0.f;

    for (int base = beg; base < end; base += 8) {
        int e = base + slot;
        int src = 0;
        float ex = 0.f;
        if (e < end) {
            src = col[e];
            ex = __expf(leaky(g_as1[src * HEADS + head] + adh));
            den += ex;
        }
        int cnt = min(8, end - base);
        int grp = lane & 24;            // head*8
        for (int j = 0; j < cnt; j++) {
            int   sj = __shfl_sync(0xffffffffu, src, j);        // from head-0 group
            float w  = __shfl_sync(0xffffffffu, ex, grp + j);   // own head's exp
            float2 f = __half22float2(g_h1h[sj * 32 + lane]);
            acc0 = fmaf(f.x, w, acc0);
            acc1 = fmaf(f.y, w, acc1);
        }
    }
    // reduce denominator within 8-lane head group
    den += __shfl_xor_sync(0xffffffffu, den, 1);
    den += __shfl_xor_sync(0xffffffffu, den, 2);
    den += __shfl_xor_sync(0xffffffffu, den, 4);

    *(float2*)&g_agg1[dst * HID + lane * 2] = make_float2(acc0 / den, acc1 / den);
}

// ---- gemm2: 128 nodes x 32 outs per block, 4x4 per thread ----------------
__global__ void gemm2_kernel(const float* __restrict__ b1,
                             const float* __restrict__ a_src,
                             const float* __restrict__ a_dst) {
    __shared__ float Wt[HID * OUT_F];   // [k][j]
    __shared__ float xs[128 * 65];      // [n][k] relu(agg1+b1), padded
    __shared__ float av[OUT_F], bv[OUT_F];
    int tid = threadIdx.x;
    int nbase = blockIdx.x * 128;

    for (int i = tid; i < HID * OUT_F; i += 256) Wt[i] = g_W2t[i];
    if (tid < OUT_F) { av[tid] = a_src[tid]; bv[tid] = a_dst[tid]; }
    for (int i = tid; i < 128 * HID; i += 256) {
        int n = i >> 6, k = i & 63;
        int node = nbase + n;
        xs[n * 65 + k] = (node < NN)
            ? fmaxf(g_agg1[node * HID + k] + __ldg(&b1[k]), 0.f) : 0.f;
    }
    __syncthreads();

    int tx = tid & 7;           // outs 4*tx .. 4*tx+3
    int ty = tid >> 3;          // nodes 4*ty .. 4*ty+3
    float acc[4][4] = {};

#pragma unroll 8
    for (int k = 0; k < HID; k++) {
        float4 w = *(const float4*)&Wt[k * OUT_F + tx * 4];
#pragma unroll
        for (int i = 0; i < 4; i++) {
            float xv = xs[(ty * 4 + i) * 65 + k];
            acc[i][0] = fmaf(xv, w.x, acc[i][0]);
            acc[i][1] = fmaf(xv, w.y, acc[i][1]);
            acc[i][2] = fmaf(xv, w.z, acc[i][2]);
            acc[i][3] = fmaf(xv, w.w, acc[i][3]);
        }
    }

    float a0 = av[tx * 4], a1 = av[tx * 4 + 1], a2 = av[tx * 4 + 2], a3 = av[tx * 4 + 3];
    float c0 = bv[tx * 4], c1 = bv[tx * 4 + 1], c2 = bv[tx * 4 + 2], c3 = bv[tx * 4 + 3];
#pragma unroll
    for (int i = 0; i < 4; i++) {
        int node = nbase + ty * 4 + i;
        float ps = acc[i][0] * a0 + acc[i][1] * a1 + acc[i][2] * a2 + acc[i][3] * a3;
        float pd = acc[i][0] * c0 + acc[i][1] * c1 + acc[i][2] * c2 + acc[i][3] * c3;
        ps += __shfl_xor_sync(0xffffffffu, ps, 1);
        ps += __shfl_xor_sync(0xffffffffu, ps, 2);
        ps += __shfl_xor_sync(0xffffffffu, ps, 4);
        pd += __shfl_xor_sync(0xffffffffu, pd, 1);
        pd += __shfl_xor_sync(0xffffffffu, pd, 2);
        pd += __shfl_xor_sync(0xffffffffu, pd, 4);
        if (node < NN) {
            __half2 p0 = __floats2half2_rn(acc[i][0], acc[i][1]);
            __half2 p1 = __floats2half2_rn(acc[i][2], acc[i][3]);
            uint2 u;
            u.x = *(unsigned int*)&p0;
            u.y = *(unsigned int*)&p1;
            *(uint2*)&g_h2h[node * 16 + tx * 2] = u;
            if (tx == 0) { g_as2[node] = ps; g_ad2[node] = pd; }
        }
    }
}

// ---- fused layer-2 softmax+aggregation (warp per dst), 2 edges / iter ----
// lane = pair*16 + feat2; lane owns features (2*feat2, 2*feat2+1).
__global__ void fused_agg2(const int* __restrict__ col,
                           const float* __restrict__ b2,
                           float* __restrict__ out) {
    int warp = (blockIdx.x * blockDim.x + threadIdx.x) >> 5;
    int lane = threadIdx.x & 31;
    if (warp >= NN) return;
    int dst = warp;
    int beg = g_rowstart[dst], end = g_rowstart[dst + 1];
    float ad = g_ad2[dst];
    int pair = lane >> 4;
    int feat2 = lane & 15;

    float acc0 = 0.f, acc1 = 0.f, den = 0.f;
    for (int base = beg; base < end; base += 32) {
        int e = base + lane;
        int src = 0;
        float ee = 0.f;
        if (e < end) {
            src = col[e];
            ee = __expf(leaky(g_as2[src] + ad));
            den += ee;
        }
        int cnt = min(32, end - base);
        for (int j = 0; j < cnt; j += 2) {
            int jj = j + pair;                                  // <= 31 always
            int   sj = __shfl_sync(0xffffffffu, src, jj);
            float w  = __shfl_sync(0xffffffffu, ee, jj);        // 0 if invalid edge
            float2 f = __half22float2(g_h2h[sj * 16 + feat2]);
            acc0 = fmaf(f.x, w, acc0);
            acc1 = fmaf(f.y, w, acc1);
        }
    }
    // merge the two pair-halves, reduce denominator over all lanes
    acc0 += __shfl_xor_sync(0xffffffffu, acc0, 16);
    acc1 += __shfl_xor_sync(0xffffffffu, acc1, 16);
#pragma unroll
    for (int off = 16; off; off >>= 1)
        den += __shfl_xor_sync(0xffffffffu, den, off);

    if (pair == 0) {
        float2 bb = *(const float2*)&b2[feat2 * 2];
        *(float2*)&out[dst * OUT_F + feat2 * 2] =
            make_float2(acc0 / den + bb.x, acc1 / den + bb.y);
    }
}

// ---------------- launch ----------------
extern "C" void kernel_launch(void* const* d_in, const int* in_sizes, int n_in,
                              void* d_out, int out_size) {
    const float* x      = (const float*)d_in[0];
    const int*   ei     = (const int*)d_in[1];
    const float* W1     = (const float*)d_in[2];
    const float* a_src1 = (const float*)d_in[3];
    const float* a_dst1 = (const float*)d_in[4];
    const float* b1     = (const float*)d_in[5];
    const float* W2     = (const float*)d_in[6];
    const float* a_src2 = (const float*)d_in[7];
    const float* a_dst2 = (const float*)d_in[8];
    const float* b2     = (const float*)d_in[9];
    float* out = (float*)d_out;

    int* d_col;
    cudaGetSymbolAddress((void**)&d_col, g_col);

    const int nodeb = (NN + 255) / 256;
    const int edgeb = (EP + 255) / 256;
    const int warpb = (NN * 32 + 255) / 256;

    init_kernel<<<nodeb, 256>>>(W1, W2);                         // 1
    hist_kernel<<<(EE + 255) / 256, 256>>>(ei);                  // 2
    scanA_kernel<<<NB, 256>>>();                                 // 3
    gemm1_kernel<<<(NN + 63) / 64, 128>>>(x, a_src1, a_dst1);    // 4  <- profiled slot
    scanB_kernel<<<1, 64>>>();                                   // 5
    scanC_kernel<<<NB, 256>>>();                                 // 6
    scatter_kernel<<<edgeb, 256>>>(ei);                          // 7
    fused_agg1<<<warpb, 256>>>(d_col);                           // 8
    gemm2_kernel<<<(NN + 127) / 128, 256>>>(b1, a_src2, a_dst2); // 9
    fused_agg2<<<warpb, 256>>>(d_col, b2, out);                  // 10
}

// round 8
// speedup vs baseline: 4.7056x; 1.0372x over previous
#include <cuda_runtime.h>
#include <cuda_bf16.h>
#include <cuda_fp16.h>
#include <math.h>

#define NN 50000
#define EE 800000
#define EP 850000      // edges + self loops
#define IN_F 64
#define HID 64
#define HEADS 4
#define OUT_F 32
#define NEG_SLOPE 0.2f

#define SCAN_CHUNK 1024
#define NB ((NN + SCAN_CHUNK - 1) / SCAN_CHUNK)   // 49 scan blocks

// ---------------- scratch (static device memory, no allocs) ----------------
__device__ float   g_W1t[IN_F * HID];    // transposed W1: [k][o]
__device__ float   g_W2t[HID * OUT_F];   // transposed W2: [k][j]
__device__ __half2 g_h1h[NN * 32];       // layer-1 features: pair (2l,2l+1)
__device__ __half2 g_h2h[NN * 16];       // layer-2 features: pair (2f,2f+1)
__device__ float   g_as1[NN * HEADS];
__device__ float   g_ad1[NN * HEADS];
__device__ float   g_agg1[NN * HID];
__device__ float   g_as2[NN];
__device__ float   g_ad2[NN];
__device__ int     g_deg[NN];
__device__ int     g_rowstart[NN + 1];
__device__ int     g_cur[NN];
__device__ int     g_col[EP];
__device__ int     g_part[NB];

__device__ __forceinline__ float leaky(float v) {
    return v > 0.f ? v : NEG_SLOPE * v;
}

// ---------------- init + weight transpose (merged) ------------------------
__global__ void init_kernel(const float* __restrict__ W1,
                            const float* __restrict__ W2) {
    int i = blockIdx.x * 256 + threadIdx.x;
    if (i < NN) g_deg[i] = 1;                       // self loop pre-counted
    if (blockIdx.x == 0) {
        int tid = threadIdx.x;
        for (int p = tid; p < IN_F * HID; p += 256) {
            int k = p >> 6, o = p & 63;
            g_W1t[k * HID + o] = W1[o * IN_F + k];
        }
        for (int p = tid; p < HID * OUT_F; p += 256) {
            int k = p >> 5, j = p & 31;
            g_W2t[k * OUT_F + j] = W2[j * HID + k];
        }
    }
}

// ---------------- CSR build ----------------
__global__ void hist_kernel(const int* __restrict__ ei) {
    int e = blockIdx.x * 256 + threadIdx.x;
    if (e < EE) atomicAdd(&g_deg[ei[EE + e]], 1);
}

__global__ void scanA_kernel() {
    __shared__ int s[256];
    int tid = threadIdx.x;
    int i0 = blockIdx.x * SCAN_CHUNK + tid * 4;
    int sum = 0;
#pragma unroll
    for (int j = 0; j < 4; j++) {
        int i = i0 + j;
        if (i < NN) sum += g_deg[i];
    }
    s[tid] = sum;
    __syncthreads();
    for (int off = 128; off; off >>= 1) {
        if (tid < off) s[tid] += s[tid + off];
        __syncthreads();
    }
    if (tid == 0) g_part[blockIdx.x] = s[0];
}

// scanC: every block redundantly scans the 49 partials (replaces scanB),
// then does its local chunk's exclusive scan, writing rowstart + cursor.
__global__ void scanC_kernel() {
    __shared__ int s[256];
    __shared__ int parts[64];
    int tid = threadIdx.x;
    if (tid < 64) parts[tid] = (tid < NB) ? g_part[tid] : 0;
    __syncthreads();
    for (int off = 1; off < 64; off <<= 1) {
        int t = (tid < 64 && tid >= off) ? parts[tid - off] : 0;
        __syncthreads();
        if (tid < 64) parts[tid] += t;
        __syncthreads();
    }
    if (blockIdx.x == 0 && tid == 0) g_rowstart[NN] = parts[NB - 1];  // = EP
    int blockpre = (blockIdx.x == 0) ? 0 : parts[blockIdx.x - 1];

    int i0 = blockIdx.x * SCAN_CHUNK + tid * 4;
    int v[4];
    int sum = 0;
#pragma unroll
    for (int j = 0; j < 4; j++) {
        int i = i0 + j;
        v[j] = (i < NN) ? g_deg[i] : 0;
        sum += v[j];
    }
    s[tid] = sum;
    __syncthreads();
    for (int off = 1; off < 256; off <<= 1) {
        int t = (tid >= off) ? s[tid - off] : 0;
        __syncthreads();
        s[tid] += t;
        __syncthreads();
    }
    int run = blockpre + s[tid] - sum;
#pragma unroll
    for (int j = 0; j < 4; j++) {
        int i = i0 + j;
        if (i < NN) {
            g_rowstart[i] = run;
            g_cur[i] = run;
            run += v[j];
        }
    }
}

__global__ void scatter_kernel(const int* __restrict__ ei) {
    int e = blockIdx.x * 256 + threadIdx.x;
    if (e >= EP) return;
    int src, dst;
    if (e < EE) { src = ei[e]; dst = ei[EE + e]; }
    else        { src = dst = e - EE; }
    int pos = atomicAdd(&g_cur[dst], 1);
    g_col[pos] = src;
}

// ---- gemm1: 64 nodes x 64 outs per block (128 thr), 8n x 4o per thread ----
__global__ void __launch_bounds__(128, 6)
gemm1_kernel(const float* __restrict__ x,
             const float* __restrict__ a_src,
             const float* __restrict__ a_dst) {
    __shared__ float Wt[IN_F * HID];    // [k][o]
    __shared__ float xs[64 * 68];       // [n][k], padded stride
    __shared__ float av[HID], bv[HID];
    int tid = threadIdx.x;
    int nbase = blockIdx.x * 64;

    for (int i = tid; i < IN_F * HID; i += 128) Wt[i] = g_W1t[i];
    if (tid < HID) { av[tid] = a_src[tid]; bv[tid] = a_dst[tid]; }
    for (int i = tid; i < 64 * IN_F; i += 128) {
        int n = i >> 6, k = i & 63;
        int node = nbase + n;
        xs[n * 68 + k] = (node < NN) ? x[node * IN_F + k] : 0.f;
    }
    __syncthreads();

    int tx = tid & 15;          // outs 4*tx .. 4*tx+3
    int ty = tid >> 4;          // nodes 8*ty .. 8*ty+7
    float acc[8][4] = {};

#pragma unroll 4
    for (int k4 = 0; k4 < IN_F; k4 += 4) {
        float4 xv[8];
#pragma unroll
        for (int i = 0; i < 8; i++)
            xv[i] = *(const float4*)&xs[(ty * 8 + i) * 68 + k4];
#pragma unroll
        for (int kk = 0; kk < 4; kk++) {
            float4 w = *(const float4*)&Wt[(k4 + kk) * HID + tx * 4];
#pragma unroll
            for (int i = 0; i < 8; i++) {
                float xvk = (kk == 0) ? xv[i].x : (kk == 1) ? xv[i].y
                          : (kk == 2) ? xv[i].z : xv[i].w;
                acc[i][0] = fmaf(xvk, w.x, acc[i][0]);
                acc[i][1] = fmaf(xvk, w.y, acc[i][1]);
                acc[i][2] = fmaf(xvk, w.z, acc[i][2]);
                acc[i][3] = fmaf(xvk, w.w, acc[i][3]);
            }
        }
    }

    float a0 = av[tx * 4], a1 = av[tx * 4 + 1], a2 = av[tx * 4 + 2], a3 = av[tx * 4 + 3];
    float c0 = bv[tx * 4], c1 = bv[tx * 4 + 1], c2 = bv[tx * 4 + 2], c3 = bv[tx * 4 + 3];
    int head = tx >> 2;
#pragma unroll
    for (int i = 0; i < 8; i++) {
        int node = nbase + ty * 8 + i;
        float ps = acc[i][0] * a0 + acc[i][1] * a1 + acc[i][2] * a2 + acc[i][3] * a3;
        float pd = acc[i][0] * c0 + acc[i][1] * c1 + acc[i][2] * c2 + acc[i][3] * c3;
        ps += __shfl_xor_sync(0xffffffffu, ps, 1);
        ps += __shfl_xor_sync(0xffffffffu, ps, 2);
        pd += __shfl_xor_sync(0xffffffffu, pd, 1);
        pd += __shfl_xor_sync(0xffffffffu, pd, 2);
        if (node < NN) {
            __half2 p0 = __floats2half2_rn(acc[i][0], acc[i][1]);
            __half2 p1 = __floats2half2_rn(acc[i][2], acc[i][3]);
            uint2 u;
            u.x = *(unsigned int*)&p0;
            u.y = *(unsigned int*)&p1;
            *(uint2*)&g_h1h[node * 32 + tx * 2] = u;
            if ((tx & 3) == 0) {
                g_as1[node * HEADS + head] = ps;
                g_ad1[node * HEADS + head] = pd;
            }
        }
    }
}

// ---- fused layer-1 softmax+aggregation (warp per dst) --------------------
// lane = head*8 + slot. Rounds of 8 edges, ALWAYS fully unrolled: lanes past
// the row end carry ex=0 / src=0, so padded iterations are zero-weight FMAs
// on a cached line. Full unroll -> 8 independent gathers in flight.
__global__ void fused_agg1(const int* __restrict__ col) {
    int warp = (blockIdx.x * blockDim.x + threadIdx.x) >> 5;
    int lane = threadIdx.x & 31;
    if (warp >= NN) return;
    int dst = warp;
    int beg = g_rowstart[dst], end = g_rowstart[dst + 1];
    int head = lane >> 3;
    int slot = lane & 7;
    int grp = lane & 24;                 // head*8
    float adh = g_ad1[dst * HEADS + head];

    float acc0 = 0.f, acc1 = 0.f, den = 0.f;

    for (int base = beg; base < end; base += 8) {
        int e = base + slot;
        int src = 0;
        float ex = 0.f;
        if (e < end) {
            src = col[e];
            ex = __expf(leaky(g_as1[src * HEADS + head] + adh));
            den += ex;
        }
#pragma unroll
        for (int j = 0; j < 8; j++) {
            int   sj = __shfl_sync(0xffffffffu, src, j);
            float w  = __shfl_sync(0xffffffffu, ex, grp + j);
            float2 f = __half22float2(g_h1h[sj * 32 + lane]);
            acc0 = fmaf(f.x, w, acc0);
            acc1 = fmaf(f.y, w, acc1);
        }
    }
    den += __shfl_xor_sync(0xffffffffu, den, 1);
    den += __shfl_xor_sync(0xffffffffu, den, 2);
    den += __shfl_xor_sync(0xffffffffu, den, 4);

    *(float2*)&g_agg1[dst * HID + lane * 2] = make_float2(acc0 / den, acc1 / den);
}

// ---- gemm2: 128 nodes x 32 outs per block, 4x4 per thread ----------------
__global__ void gemm2_kernel(const float* __restrict__ b1,
                             const float* __restrict__ a_src,
                             const float* __restrict__ a_dst) {
    __shared__ float Wt[HID * OUT_F];   // [k][j]
    __shared__ float xs[128 * 65];      // [n][k] relu(agg1+b1), padded
    __shared__ float av[OUT_F], bv[OUT_F];
    int tid = threadIdx.x;
    int nbase = blockIdx.x * 128;

    for (int i = tid; i < HID * OUT_F; i += 256) Wt[i] = g_W2t[i];
    if (tid < OUT_F) { av[tid] = a_src[tid]; bv[tid] = a_dst[tid]; }
    for (int i = tid; i < 128 * HID; i += 256) {
        int n = i >> 6, k = i & 63;
        int node = nbase + n;
        xs[n * 65 + k] = (node < NN)
            ? fmaxf(g_agg1[node * HID + k] + __ldg(&b1[k]), 0.f) : 0.f;
    }
    __syncthreads();

    int tx = tid & 7;           // outs 4*tx .. 4*tx+3
    int ty = tid >> 3;          // nodes 4*ty .. 4*ty+3
    float acc[4][4] = {};

#pragma unroll 8
    for (int k = 0; k < HID; k++) {
        float4 w = *(const float4*)&Wt[k * OUT_F + tx * 4];
#pragma unroll
        for (int i = 0; i < 4; i++) {
            float xv = xs[(ty * 4 + i) * 65 + k];
            acc[i][0] = fmaf(xv, w.x, acc[i][0]);
            acc[i][1] = fmaf(xv, w.y, acc[i][1]);
            acc[i][2] = fmaf(xv, w.z, acc[i][2]);
            acc[i][3] = fmaf(xv, w.w, acc[i][3]);
        }
    }

    float a0 = av[tx * 4], a1 = av[tx * 4 + 1], a2 = av[tx * 4 + 2], a3 = av[tx * 4 + 3];
    float c0 = bv[tx * 4], c1 = bv[tx * 4 + 1], c2 = bv[tx * 4 + 2], c3 = bv[tx * 4 + 3];
#pragma unroll
    for (int i = 0; i < 4; i++) {
        int node = nbase + ty * 4 + i;
        float ps = acc[i][0] * a0 + acc[i][1] * a1 + acc[i][2] * a2 + acc[i][3] * a3;
        float pd = acc[i][0] * c0 + acc[i][1] * c1 + acc[i][2] * c2 + acc[i][3] * c3;
        ps += __shfl_xor_sync(0xffffffffu, ps, 1);
        ps += __shfl_xor_sync(0xffffffffu, ps, 2);
        ps += __shfl_xor_sync(0xffffffffu, ps, 4);
        pd += __shfl_xor_sync(0xffffffffu, pd, 1);
        pd += __shfl_xor_sync(0xffffffffu, pd, 2);
        pd += __shfl_xor_sync(0xffffffffu, pd, 4);
        if (node < NN) {
            __half2 p0 = __floats2half2_rn(acc[i][0], acc[i][1]);
            __half2 p1 = __floats2half2_rn(acc[i][2], acc[i][3]);
            uint2 u;
            u.x = *(unsigned int*)&p0;
            u.y = *(unsigned int*)&p1;
            *(uint2*)&g_h2h[node * 16 + tx * 2] = u;
            if (tx == 0) { g_as2[node] = ps; g_ad2[node] = pd; }
        }
    }
}

// ---- fused layer-2 softmax+aggregation (warp per dst), fully unrolled ----
// lane = pair*16 + feat2; rounds of 32 edges, 16 pair-iterations, always
// fully unrolled with zero-weight padding.
__global__ void fused_agg2(const int* __restrict__ col,
                           const float* __restrict__ b2,
                           float* __restrict__ out) {
    int warp = (blockIdx.x * blockDim.x + threadIdx.x) >> 5;
    int lane = threadIdx.x & 31;
    if (warp >= NN) return;
    int dst = warp;
    int beg = g_rowstart[dst], end = g_rowstart[dst + 1];
    float ad = g_ad2[dst];
    int pair = lane >> 4;
    int feat2 = lane & 15;

    float acc0 = 0.f, acc1 = 0.f, den = 0.f;
    for (int base = beg; base < end; base += 32) {
        int e = base + lane;
        int src = 0;
        float ee = 0.f;
        if (e < end) {
            src = col[e];
            ee = __expf(leaky(g_as2[src] + ad));
            den += ee;
        }
#pragma unroll
        for (int j = 0; j < 32; j += 2) {
            int jj = j + pair;
            int   sj = __shfl_sync(0xffffffffu, src, jj);
            float w  = __shfl_sync(0xffffffffu, ee, jj);   // 0 if padded edge
            float2 f = __half22float2(g_h2h[sj * 16 + feat2]);
            acc0 = fmaf(f.x, w, acc0);
            acc1 = fmaf(f.y, w, acc1);
        }
    }
    acc0 += __shfl_xor_sync(0xffffffffu, acc0, 16);
    acc1 += __shfl_xor_sync(0xffffffffu, acc1, 16);
#pragma unroll
    for (int off = 16; off; off >>= 1)
        den += __shfl_xor_sync(0xffffffffu, den, off);

    if (pair == 0) {
        float2 bb = *(const float2*)&b2[feat2 * 2];
        *(float2*)&out[dst * OUT_F + feat2 * 2] =
            make_float2(acc0 / den + bb.x, acc1 / den + bb.y);
    }
}

// ---------------- launch ----------------
extern "C" void kernel_launch(void* const* d_in, const int* in_sizes, int n_in,
                              void* d_out, int out_size) {
    const float* x      = (const float*)d_in[0];
    const int*   ei     = (const int*)d_in[1];
    const float* W1     = (const float*)d_in[2];
    const float* a_src1 = (const float*)d_in[3];
    const float* a_dst1 = (const float*)d_in[4];
    const float* b1     = (const float*)d_in[5];
    const float* W2     = (const float*)d_in[6];
    const float* a_src2 = (const float*)d_in[7];
    const float* a_dst2 = (const float*)d_in[8];
    const float* b2     = (const float*)d_in[9];
    float* out = (float*)d_out;

    int* d_col;
    cudaGetSymbolAddress((void**)&d_col, g_col);

    const int nodeb = (NN + 255) / 256;
    const int edgeb = (EP + 255) / 256;
    const int warpb = (NN * 32 + 255) / 256;

    init_kernel<<<nodeb, 256>>>(W1, W2);                         // 1
    hist_kernel<<<(EE + 255) / 256, 256>>>(ei);                  // 2
    scanA_kernel<<<NB, 256>>>();                                 // 3
    gemm1_kernel<<<(NN + 63) / 64, 128>>>(x, a_src1, a_dst1);    // 4  <- profiled slot
    scanC_kernel<<<NB, 256>>>();                                 // 5
    scatter_kernel<<<edgeb, 256>>>(ei);                          // 6
    fused_agg1<<<warpb, 256>>>(d_col);                           // 7
    gemm2_kernel<<<(NN + 127) / 128, 256>>>(b1, a_src2, a_dst2); // 8
    fused_agg2<<<warpb, 256>>>(d_col, b2, out);                  // 9
}